// round 8
// baseline (speedup 1.0000x reference)
#include <cuda_runtime.h>
#include <cuda_bf16.h>
#include <math.h>
#include <stdint.h>

#define BATCH 16
#define CINC 64
#define HH 128
#define WW 128
#define HW 16384
#define NCLS 80
#define KTOP 100

// ---------------- device scratch ----------------
__device__ float g_featc[BATCH * 64 * HW];
__device__ float g_score[BATCH * HW];
__device__ int   g_cat  [BATCH * HW];
__device__ float g_tscore[BATCH * KTOP];
__device__ int   g_tind  [BATCH * KTOP];
__device__ float g_boxes[BATCH * KTOP * 4];

// bf16 split inputs: [s][b][R 0..129][px*64+cin]; R=0/129 zero pad rows
#define XS_PER_SPLIT ((size_t)BATCH * 130 * 8192)
__device__ __nv_bfloat16 g_xs[3 * XS_PER_SPLIT];
// bf16 split weights: [(ky*3+kx)*3+s][oc*64+cin]
__device__ __nv_bfloat16 g_ws[27 * 4096];

// ---------------- f32x2 helpers ----------------
__device__ __forceinline__ unsigned long long pk2(float lo, float hi) {
    unsigned long long r;
    asm("mov.b64 %0, {%1, %2};" : "=l"(r) : "r"(__float_as_uint(lo)), "r"(__float_as_uint(hi)));
    return r;
}
__device__ __forceinline__ unsigned long long fma2(unsigned long long a, unsigned long long b,
                                                   unsigned long long c) {
    unsigned long long d;
    asm("fma.rn.f32x2 %0, %1, %2, %3;" : "=l"(d) : "l"(a), "l"(b), "l"(c));
    return d;
}
__device__ __forceinline__ float2 upk(unsigned long long v) {
    unsigned int a, b;
    asm("mov.b64 {%0, %1}, %2;" : "=r"(a), "=r"(b) : "l"(v));
    return make_float2(__uint_as_float(a), __uint_as_float(b));
}

// ---------------- warp-mma helpers (baseline PTX, no 'a' features) ----------------
__device__ __forceinline__ uint32_t smem_u32(const void* p) {
    uint32_t a;
    asm("{ .reg .u64 t; cvta.to.shared.u64 t, %1; cvt.u32.u64 %0, t; }" : "=r"(a) : "l"(p));
    return a;
}
__device__ __forceinline__ void ldsm_x4(uint32_t* r, uint32_t addr) {
    asm volatile("ldmatrix.sync.aligned.m8n8.x4.shared.b16 {%0,%1,%2,%3}, [%4];"
        : "=r"(r[0]), "=r"(r[1]), "=r"(r[2]), "=r"(r[3]) : "r"(addr));
}
__device__ __forceinline__ void mma16816(float* d, const uint32_t* a, const uint32_t* b) {
    asm volatile(
        "mma.sync.aligned.m16n8k16.row.col.f32.bf16.bf16.f32 "
        "{%0,%1,%2,%3}, {%4,%5,%6,%7}, {%8,%9}, {%0,%1,%2,%3};"
        : "+f"(d[0]), "+f"(d[1]), "+f"(d[2]), "+f"(d[3])
        : "r"(a[0]), "r"(a[1]), "r"(a[2]), "r"(a[3]), "r"(b[0]), "r"(b[1]));
}
#define SW128(o) ((o) ^ (((o) >> 3) & 0x70))

// =====================================================================
// Prep 1: split x into 3 bf16 parts, layout [s][b][R][px*64+cin]
// =====================================================================
__global__ __launch_bounds__(256) void xsplit_kernel(const float* __restrict__ x)
{
    __shared__ float tile[64 * 128];
    const int R = blockIdx.x, b = blockIdx.y;
    const int tid = threadIdx.x;
    const bool valid = (R >= 1 && R <= 128);

    if (valid) {
        const float* src = x + ((size_t)b * 64 * 128 + (R - 1)) * 128;
        for (int e = tid; e < 8192; e += 256) {
            int cin = e >> 7, px = e & 127;
            tile[e] = src[(size_t)cin * HW + px];
        }
    }
    __syncthreads();

    size_t base = ((size_t)b * 130 + R) * 8192;
    for (int e = tid; e < 8192; e += 256) {
        float f = 0.f;
        if (valid) {
            int px = e >> 6, cin = e & 63;
            f = tile[cin * 128 + px];
        }
        __nv_bfloat16 h1 = __float2bfloat16_rn(f);
        float r1 = f - __bfloat162float(h1);
        __nv_bfloat16 h2 = __float2bfloat16_rn(r1);
        float r2 = r1 - __bfloat162float(h2);
        __nv_bfloat16 h3 = __float2bfloat16_rn(r2);
        g_xs[base + e]                    = h1;
        g_xs[XS_PER_SPLIT + base + e]     = h2;
        g_xs[2 * XS_PER_SPLIT + base + e] = h3;
    }
}

// =====================================================================
// Prep 2: split weights
// =====================================================================
__global__ __launch_bounds__(256) void wsplit_kernel(const float* __restrict__ w1)
{
    const int ts = blockIdx.x;       // tap*3+s
    const int tap = ts / 3, s = ts - tap * 3;
    const int ky = tap / 3, kx = tap - ky * 3;
    const int tid = threadIdx.x;
    for (int e = tid; e < 4096; e += 256) {
        int oc = e >> 6, cin = e & 63;
        float f = w1[oc * 576 + cin * 9 + ky * 3 + kx];
        __nv_bfloat16 h1 = __float2bfloat16_rn(f);
        float r1 = f - __bfloat162float(h1);
        __nv_bfloat16 h2 = __float2bfloat16_rn(r1);
        float r2 = r1 - __bfloat162float(h2);
        __nv_bfloat16 h3 = __float2bfloat16_rn(r2);
        __nv_bfloat16 out = (s == 0) ? h1 : (s == 1) ? h2 : h3;
        g_ws[(size_t)ts * 4096 + e] = out;
    }
}

// =====================================================================
// conv via warp-level mma.sync (bf16, 6-term split), 3 kx passes with
// gmem fp32 accumulation. CTA=(rowgroup of 8, batch), 8 warps.
// =====================================================================
#define B_OFF 0
#define A_OFF 73728
#define CONV_SMEM 221184

__device__ __forceinline__ void ld_a_row(uint4* pf, int b, int R, int kx, int tid) {
    #pragma unroll
    for (int j = 0; j < 12; j++) {
        int c = j * 256 + tid;                 // 0..3071
        int s_x = c >> 10;
        uint32_t o = (uint32_t)(c & 1023) * 16;
        int px = (int)(o >> 7);
        int within = (int)(o & 127);
        int px_src = px + kx - 1;
        uint4 v = make_uint4(0, 0, 0, 0);
        if (px_src >= 0 && px_src < 128) {
            const char* src = (const char*)(g_xs + (size_t)s_x * XS_PER_SPLIT
                              + ((size_t)b * 130 + R) * 8192)
                              + (size_t)px_src * 128 + within;
            v = __ldg((const uint4*)src);
        }
        pf[j] = v;
    }
}
__device__ __forceinline__ void st_a_row(const uint4* pf, char* smem, int slot, int tid) {
    #pragma unroll
    for (int j = 0; j < 12; j++) {
        int c = j * 256 + tid;
        int s_x = c >> 10;
        uint32_t o = (uint32_t)(c & 1023) * 16;
        *(uint4*)(smem + A_OFF + slot * 49152 + s_x * 16384 + SW128(o)) = pf[j];
    }
}

__global__ __launch_bounds__(256, 1) void conv_mma_kernel(const float* __restrict__ b1)
{
    extern __shared__ char smem[];
    const uint32_t sb = smem_u32(smem);
    const int g = blockIdx.x, b = blockIdx.y;
    const int tid = threadIdx.x;
    const int w = tid >> 5, lane = tid & 31;
    const int Y0 = g * 8;
    const int q = lane >> 3, rr = lane & 7;

    // ldmatrix logical base offsets (unswizzled)
    const uint32_t a_base = (uint32_t)((w * 16 + rr + 8 * (q & 1)) * 128 + 16 * (q >> 1));
    const uint32_t b_base = (uint32_t)((8 * (q >> 1) + rr) * 128 + 16 * (q & 1));
    // D fragment coords
    const int px0 = w * 16 + (lane >> 2);
    const int oc0 = 2 * (lane & 3);
    float* gout = g_featc + (size_t)b * 64 * HW;

    for (int kx = 0; kx < 3; kx++) {
        // stage B tiles (ky, s_w) for this kx
        for (int idx = tid; idx < 9 * 512; idx += 256) {
            int t = idx >> 9;
            int ky = t / 3, s_w = t - ky * 3;
            uint32_t o = (uint32_t)(idx & 511) * 16;
            const char* src = (const char*)(g_ws + (size_t)((ky * 3 + kx) * 3 + s_w) * 4096) + o;
            *(uint4*)(smem + B_OFF + t * 8192 + SW128(o)) = *(const uint4*)src;
        }
        // pre-stage A rows Y0..Y0+2 into ring slots R%3
        for (int R = Y0; R < Y0 + 3; R++) {
            uint4 pf0[12];
            ld_a_row(pf0, b, R, kx, tid);
            st_a_row(pf0, smem, R % 3, tid);
        }
        __syncthreads();

        for (int r0 = 0; r0 < 8; r0++) {
            const int y = Y0 + r0;
            uint4 pf[12];
            if (r0 < 7) ld_a_row(pf, b, y + 3, kx, tid);

            float acc[8][4];
            #pragma unroll
            for (int i = 0; i < 8; i++)
                #pragma unroll
                for (int j = 0; j < 4; j++) acc[i][j] = 0.f;

            for (int ky = 0; ky < 3; ky++) {
                const uint32_t slotb = sb + A_OFF + (uint32_t)(((y + ky) % 3) * 49152);
                #pragma unroll
                for (int kc = 0; kc < 4; kc++) {
                    uint32_t a0[4], a1[4], a2[4];
                    ldsm_x4(a0, slotb +          SW128(a_base + 32 * kc));
                    ldsm_x4(a1, slotb + 16384u + SW128(a_base + 32 * kc));
                    ldsm_x4(a2, slotb + 32768u + SW128(a_base + 32 * kc));
                    #pragma unroll
                    for (int s_w = 0; s_w < 3; s_w++) {
                        const uint32_t tile = sb + B_OFF + (uint32_t)((ky * 3 + s_w) * 8192);
                        #pragma unroll
                        for (int nt2 = 0; nt2 < 4; nt2++) {
                            uint32_t bb[4];
                            ldsm_x4(bb, tile + SW128(b_base + nt2 * 2048u + 32 * kc));
                            mma16816(acc[nt2 * 2],     a0, bb);
                            mma16816(acc[nt2 * 2 + 1], a0, bb + 2);
                            if (s_w < 2) {
                                mma16816(acc[nt2 * 2],     a1, bb);
                                mma16816(acc[nt2 * 2 + 1], a1, bb + 2);
                            }
                            if (s_w < 1) {
                                mma16816(acc[nt2 * 2],     a2, bb);
                                mma16816(acc[nt2 * 2 + 1], a2, bb + 2);
                            }
                        }
                    }
                }
            }

            // epilogue: accumulate into g_featc across kx passes
            #pragma unroll
            for (int nt = 0; nt < 8; nt++) {
                const int oc = nt * 8 + oc0;
                float* p0 = gout + (size_t)oc * HW + y * 128 + px0;
                float* p1 = p0 + HW;
                if (kx == 0) {
                    p0[0] = acc[nt][0]; p1[0] = acc[nt][1];
                    p0[8] = acc[nt][2]; p1[8] = acc[nt][3];
                } else if (kx == 1) {
                    p0[0] += acc[nt][0]; p1[0] += acc[nt][1];
                    p0[8] += acc[nt][2]; p1[8] += acc[nt][3];
                } else {
                    const float ba = __ldg(b1 + oc), bb2 = __ldg(b1 + oc + 1);
                    p0[0] = fmaxf(p0[0] + acc[nt][0] + ba,  0.f);
                    p1[0] = fmaxf(p1[0] + acc[nt][1] + bb2, 0.f);
                    p0[8] = fmaxf(p0[8] + acc[nt][2] + ba,  0.f);
                    p1[8] = fmaxf(p1[8] + acc[nt][3] + bb2, 0.f);
                }
            }
            __syncthreads();
            if (r0 < 7) st_a_row(pf, smem, (y + 3) % 3, tid);
            __syncthreads();
        }
    }
}

// =====================================================================
// Fused 1x1 conv (64->80) + sigmoid + 3x3 peak + argmax (unchanged)
// =====================================================================
#define CLS_STRIDE 328
__global__ __launch_bounds__(352, 1) void clspeak_kernel(
    const float* __restrict__ w2, const float* __restrict__ b2)
{
    __shared__ float s_w[80 * 64];
    __shared__ float s_b[80];
    __shared__ float s_cls[20 * CLS_STRIDE];

    const int tx = blockIdx.x, ty = blockIdx.y, b = blockIdx.z;
    const int ox = tx * 16, oy = ty * 16;
    const int tid = threadIdx.x;
    const float NEG = -1e30f;

    for (int e = tid; e < 80 * 64; e += 352) s_w[e] = w2[e];
    if (tid < 80) s_b[tid] = b2[tid];

    unsigned long long fd[32];
    bool inimg = false;
    if (tid < 324) {
        int iy = tid / 18, ix = tid - iy * 18;
        int gy = oy + iy - 1, gx = ox + ix - 1;
        inimg = (gy >= 0 && gy < HH && gx >= 0 && gx < WW);
        const float* fp = g_featc + (size_t)b * 64 * HW + gy * WW + gx;
        #pragma unroll
        for (int i = 0; i < 32; i++) {
            float a = inimg ? fp[(2 * i) * HW]     : 0.f;
            float c = inimg ? fp[(2 * i + 1) * HW] : 0.f;
            fd[i] = pk2(a, c);
        }
    }
    __syncthreads();

    const int py = (tid >> 4) + 1, px = (tid & 15) + 1;
    const int pp = py * 18 + px;
    float best = -1.f;
    int cat = 0;

    for (int g = 0; g < 4; g++) {
        if (tid < 324) {
            #pragma unroll
            for (int cp = 0; cp < 10; cp++) {
                const int c0 = g * 20 + 2 * cp;
                unsigned long long a0 = 0ull, a1 = 0ull;
                const ulonglong2* w0 = (const ulonglong2*)(s_w + c0 * 64);
                const ulonglong2* w1 = (const ulonglong2*)(s_w + (c0 + 1) * 64);
                #pragma unroll
                for (int i = 0; i < 16; i++) {
                    ulonglong2 wa = w0[i];
                    ulonglong2 wb = w1[i];
                    a0 = fma2(fd[2 * i],     wa.x, a0);
                    a0 = fma2(fd[2 * i + 1], wa.y, a0);
                    a1 = fma2(fd[2 * i],     wb.x, a1);
                    a1 = fma2(fd[2 * i + 1], wb.y, a1);
                }
                float2 u0 = upk(a0), u1 = upk(a1);
                float v0 = u0.x + u0.y + s_b[c0];
                float v1 = u1.x + u1.y + s_b[c0 + 1];
                v0 = 1.f / (1.f + expf(-v0));
                v1 = 1.f / (1.f + expf(-v1));
                if (!inimg) { v0 = NEG; v1 = NEG; }
                s_cls[(2 * cp)     * CLS_STRIDE + tid] = v0;
                s_cls[(2 * cp + 1) * CLS_STRIDE + tid] = v1;
            }
        }
        __syncthreads();
        if (tid < 256) {
            #pragma unroll 4
            for (int c = 0; c < 20; c++) {
                const float* row = s_cls + c * CLS_STRIDE;
                float v = row[pp];
                float m = v;
                m = fmaxf(m, row[pp - 19]); m = fmaxf(m, row[pp - 18]); m = fmaxf(m, row[pp - 17]);
                m = fmaxf(m, row[pp - 1]);                               m = fmaxf(m, row[pp + 1]);
                m = fmaxf(m, row[pp + 17]); m = fmaxf(m, row[pp + 18]); m = fmaxf(m, row[pp + 19]);
                float k = (v == m) ? v : 0.f;
                if (k > best) { best = k; cat = g * 20 + c; }
            }
        }
        __syncthreads();
    }

    if (tid < 256) {
        int gp = (oy + py - 1) * WW + ox + px - 1;
        g_score[b * HW + gp] = best;
        g_cat[b * HW + gp]   = cat;
    }
}

// =====================================================================
// top-100 (unchanged)
// =====================================================================
#define TOPK_SMEM (8192 * 4 + 1024 * 4 + HW * 8)
__global__ __launch_bounds__(1024) void topk_kernel()
{
    extern __shared__ int smi[];
    int* hist = smi;
    int* suf  = smi + 8192;
    unsigned long long* cand = (unsigned long long*)(smi + 8192 + 1024);
    __shared__ int s_tstar, s_T, s_cnt;

    const int b = blockIdx.x;
    const int tid = threadIdx.x;
    const float* s = g_score + b * HW;

    for (int i = tid; i < 8192; i += 1024) hist[i] = 0;
    if (tid == 0) s_cnt = 0;
    __syncthreads();

    for (int j = tid; j < HW; j += 1024) {
        unsigned int u = __float_as_uint(s[j]);
        atomicAdd(&hist[u >> 19], 1);
    }
    __syncthreads();

    int seg = 0;
    #pragma unroll
    for (int k = 0; k < 8; k++) seg += hist[tid * 8 + k];
    suf[tid] = seg;
    __syncthreads();
    for (int off = 1; off < 1024; off <<= 1) {
        int v = suf[tid];
        int add = (tid + off < 1024) ? suf[tid + off] : 0;
        __syncthreads();
        suf[tid] = v + add;
        __syncthreads();
    }
    if (suf[tid] >= KTOP && (tid == 1023 || suf[tid + 1] < KTOP)) s_tstar = tid;
    __syncthreads();
    if (tid == s_tstar) {
        int acc = (tid == 1023) ? 0 : suf[tid + 1];
        for (int bb = tid * 8 + 7; bb >= tid * 8; bb--) {
            acc += hist[bb];
            if (acc >= KTOP) { s_T = bb; break; }
        }
    }
    __syncthreads();
    const int T = s_T;

    for (int j = tid; j < HW; j += 1024) {
        unsigned int u = __float_as_uint(s[j]);
        if ((int)(u >> 19) >= T) {
            int pos = atomicAdd(&s_cnt, 1);
            cand[pos] = ((unsigned long long)u << 32) | (unsigned long long)(HW - j);
        }
    }
    __syncthreads();
    const int N = s_cnt;

    for (int i = tid; i < N; i += 1024) {
        unsigned long long key = cand[i];
        int rank = 0;
        for (int j = 0; j < N; j++) rank += (cand[j] > key);
        if (rank < KTOP) {
            g_tscore[b * KTOP + rank] = __uint_as_float((unsigned int)(key >> 32));
            g_tind[b * KTOP + rank]   = HW - (int)(key & 0xFFFFFFFFull);
        }
    }
}

// =====================================================================
// reg/wh at selected points (unchanged)
// =====================================================================
#define PTS 5
__global__ __launch_bounds__(128) void point_kernel(
    const float* __restrict__ x,
    const float* __restrict__ rw1, const float* __restrict__ rb1,
    const float* __restrict__ rw2, const float* __restrict__ rb2,
    const float* __restrict__ ww1, const float* __restrict__ wb1,
    const float* __restrict__ ww2, const float* __restrict__ wb2)
{
    __shared__ float sx[PTS][576];
    __shared__ int   sp[PTS];
    __shared__ float sfa[128][PTS + 1];
    __shared__ float sres[PTS][4];

    const int g = blockIdx.x, b = blockIdx.y;
    const int tid = threadIdx.x;

    if (tid < PTS) sp[tid] = g_tind[b * KTOP + g * PTS + tid];
    __syncthreads();

    for (int e = tid; e < PTS * 576; e += 128) {
        int pt = e / 576;
        int r  = e - pt * 576;
        int c  = r / 9;
        int k9 = r - c * 9;
        int dy = k9 / 3 - 1, dx = k9 % 3 - 1;
        int p = sp[pt];
        int gy = (p >> 7) + dy, gx = (p & 127) + dx;
        float v = 0.f;
        if (gy >= 0 && gy < HH && gx >= 0 && gx < WW)
            v = x[((size_t)b * CINC + c) * HW + gy * WW + gx];
        sx[pt][r] = v;
    }
    __syncthreads();

    const float* wrow = (tid < 64) ? (rw1 + tid * 576) : (ww1 + (tid - 64) * 576);
    float bias = (tid < 64) ? rb1[tid] : wb1[tid - 64];
    float acc[PTS];
    #pragma unroll
    for (int pt = 0; pt < PTS; pt++) acc[pt] = bias;

    for (int j = 0; j < 576; j += 4) {
        float4 w4 = *(const float4*)(wrow + j);
        #pragma unroll
        for (int q = 0; q < 4; q++) {
            float w = (q == 0) ? w4.x : (q == 1) ? w4.y : (q == 2) ? w4.z : w4.w;
            #pragma unroll
            for (int pt = 0; pt < PTS; pt++)
                acc[pt] = fmaf(w, sx[pt][j + q], acc[pt]);
        }
    }
    #pragma unroll
    for (int pt = 0; pt < PTS; pt++) sfa[tid][pt] = fmaxf(acc[pt], 0.f);
    __syncthreads();

    if (tid < PTS * 4) {
        int pt = tid >> 2, o = tid & 3;
        float sv;
        if (o < 2) {
            sv = rb2[o];
            for (int i = 0; i < 64; i++) sv = fmaf(sfa[i][pt], rw2[o * 64 + i], sv);
            sv = 1.f / (1.f + expf(-sv));
        } else {
            int oo = o - 2;
            sv = wb2[oo];
            for (int i = 0; i < 64; i++) sv = fmaf(sfa[64 + i][pt], ww2[oo * 64 + i], sv);
            sv = expf(sv);
        }
        sres[pt][o] = sv;
    }
    __syncthreads();

    if (tid < PTS) {
        int p = sp[tid];
        float cx = (float)(p & 127) + sres[tid][0];
        float cy = (float)(p >> 7)  + sres[tid][1];
        float wv = sres[tid][2], hv = sres[tid][3];
        int k = b * KTOP + g * PTS + tid;
        g_boxes[k * 4 + 0] = (cx - wv * 0.5f) * 4.f;
        g_boxes[k * 4 + 1] = (cy - hv * 0.5f) * 4.f;
        g_boxes[k * 4 + 2] = (cx + wv * 0.5f) * 4.f;
        g_boxes[k * 4 + 3] = (cy + hv * 0.5f) * 4.f;
    }
}

// =====================================================================
// NMS + output (unchanged)
// =====================================================================
__global__ __launch_bounds__(128) void nms_kernel(float* __restrict__ out)
{
    const int b = blockIdx.x;
    const int tid = threadIdx.x;
    __shared__ float bx[KTOP][4];
    __shared__ float barea[KTOP];
    __shared__ int keep[KTOP];

    float score = 0.f; int cat = 0;
    if (tid < KTOP) {
        int k = b * KTOP + tid;
        score = g_tscore[k];
        cat   = g_cat[b * HW + g_tind[k]];
        float x1 = g_boxes[k * 4 + 0], y1 = g_boxes[k * 4 + 1];
        float x2 = g_boxes[k * 4 + 2], y2 = g_boxes[k * 4 + 3];
        bx[tid][0] = x1; bx[tid][1] = y1; bx[tid][2] = x2; bx[tid][3] = y2;
        barea[tid] = (x2 - x1) * (y2 - y1);
        keep[tid] = (score > 0.2f) ? 1 : 0;
    }
    __syncthreads();

    for (int i = 0; i < KTOP - 1; i++) {
        if (tid < KTOP && tid > i && keep[i]) {
            float xx1 = fmaxf(bx[i][0], bx[tid][0]);
            float yy1 = fmaxf(bx[i][1], bx[tid][1]);
            float xx2 = fminf(bx[i][2], bx[tid][2]);
            float yy2 = fminf(bx[i][3], bx[tid][3]);
            float iw = fmaxf(xx2 - xx1, 0.f);
            float ih = fmaxf(yy2 - yy1, 0.f);
            float inter = iw * ih;
            float iou = inter / (barea[i] + barea[tid] - inter + 1e-9f);
            if (iou > 0.5f) keep[tid] = 0;
        }
        __syncthreads();
    }

    if (tid < KTOP) {
        int base = b * KTOP + tid;
        out[base * 4 + 0] = bx[tid][0];
        out[base * 4 + 1] = bx[tid][1];
        out[base * 4 + 2] = bx[tid][2];
        out[base * 4 + 3] = bx[tid][3];
        out[6400 + base] = (float)cat;
        out[8000 + base] = score;
        out[9600 + base] = keep[tid] ? 1.f : 0.f;
    }
}

// =====================================================================
extern "C" void kernel_launch(void* const* d_in, const int* in_sizes, int n_in,
                              void* d_out, int out_size)
{
    const float* x      = (const float*)d_in[0];
    const float* cls_w1 = (const float*)d_in[1];
    const float* cls_b1 = (const float*)d_in[2];
    const float* cls_w2 = (const float*)d_in[3];
    const float* cls_b2 = (const float*)d_in[4];
    const float* reg_w1 = (const float*)d_in[5];
    const float* reg_b1 = (const float*)d_in[6];
    const float* reg_w2 = (const float*)d_in[7];
    const float* reg_b2 = (const float*)d_in[8];
    const float* wh_w1  = (const float*)d_in[9];
    const float* wh_b1  = (const float*)d_in[10];
    const float* wh_w2  = (const float*)d_in[11];
    const float* wh_b2  = (const float*)d_in[12];
    float* out = (float*)d_out;

    cudaFuncSetAttribute(conv_mma_kernel, cudaFuncAttributeMaxDynamicSharedMemorySize, CONV_SMEM);
    cudaFuncSetAttribute(topk_kernel, cudaFuncAttributeMaxDynamicSharedMemorySize, TOPK_SMEM);

    xsplit_kernel<<<dim3(130, BATCH), 256>>>(x);
    wsplit_kernel<<<27, 256>>>(cls_w1);
    conv_mma_kernel<<<dim3(16, BATCH), 256, CONV_SMEM>>>(cls_b1);
    clspeak_kernel<<<dim3(8, 8, BATCH), 352>>>(cls_w2, cls_b2);
    topk_kernel<<<BATCH, 1024, TOPK_SMEM>>>();
    point_kernel<<<dim3(20, BATCH), 128>>>(x, reg_w1, reg_b1, reg_w2, reg_b2,
                                           wh_w1, wh_b1, wh_w2, wh_b2);
    nms_kernel<<<BATCH, 128>>>(out);
}

// round 9
// speedup vs baseline: 1.1140x; 1.1140x over previous
#include <cuda_runtime.h>
#include <math.h>
#include <stdint.h>

#define BATCH 16
#define CINC 64
#define HH 128
#define WW 128
#define HW 16384
#define NCLS 80
#define KTOP 100

// ---------------- device scratch ----------------
__device__ float g_featc[BATCH * 64 * HW];   // relu(conv3x3) cls branch
__device__ float g_score[BATCH * HW];
__device__ int   g_cat  [BATCH * HW];
__device__ float g_tscore[BATCH * KTOP];
__device__ int   g_tind  [BATCH * KTOP];
__device__ float g_boxes[BATCH * KTOP * 4];
__device__ float g_wt[576 * 64];             // cls_w1 transposed: [rem 0..575][oc 0..63]

// ---------------- f32x2 helpers ----------------
__device__ __forceinline__ unsigned long long pk2(float lo, float hi) {
    unsigned long long r;
    asm("mov.b64 %0, {%1, %2};" : "=l"(r) : "r"(__float_as_uint(lo)), "r"(__float_as_uint(hi)));
    return r;
}
__device__ __forceinline__ unsigned long long dup2(float x) { return pk2(x, x); }
__device__ __forceinline__ unsigned long long fma2(unsigned long long a, unsigned long long b,
                                                   unsigned long long c) {
    unsigned long long d;
    asm("fma.rn.f32x2 %0, %1, %2, %3;" : "=l"(d) : "l"(a), "l"(b), "l"(c));
    return d;
}
__device__ __forceinline__ float2 upk(unsigned long long v) {
    unsigned int a, b;
    asm("mov.b64 {%0, %1}, %2;" : "=r"(a), "=r"(b) : "l"(v));
    return make_float2(__uint_as_float(a), __uint_as_float(b));
}

// =====================================================================
// Prep: transpose cls conv1 weights -> [rem][oc] for coalesced staging
// =====================================================================
__global__ __launch_bounds__(256) void wprep_kernel(const float* __restrict__ w1)
{
    int i = blockIdx.x * 256 + threadIdx.x;
    if (i < 64 * 576) {
        int oc = i / 576, rem = i - oc * 576;
        g_wt[rem * 64 + oc] = w1[i];
    }
}

// =====================================================================
// Kernel 1: 3x3 conv (64 -> 64, cls branch) + bias + relu, f32x2.
// 16x16 tile, 256 threads; thread = 8 px (x) x 4 oc (2 oc-pairs).
// Weights staged from pre-transposed g_wt (coalesced uint4 copies).
// =====================================================================
#define SIN_WORDS (64 * 18 * 20)
#define SW_WORDS  (576 * 32)
#define CONV1_SMEM ((SIN_WORDS + SW_WORDS) * 4)

__global__ __launch_bounds__(256, 1) void conv1_kernel(
    const float* __restrict__ x, const float* __restrict__ b1)
{
    extern __shared__ float sm[];
    float* s_in = sm;
    float* s_w  = sm + SIN_WORDS;

    const int tx = blockIdx.x, ty = blockIdx.y, b = blockIdx.z;
    const int ox = tx * 16, oy = ty * 16;
    const int tid = threadIdx.x;
    const float* xb = x + (size_t)b * CINC * HW;

    for (int e = tid; e < 64 * 324; e += 256) {
        int c   = e / 324;
        int rem = e - c * 324;
        int iy  = rem / 18;
        int ix  = rem - iy * 18;
        int gy = oy + iy - 1, gx = ox + ix - 1;
        float v = 0.f;
        if (gy >= 0 && gy < HH && gx >= 0 && gx < WW)
            v = xb[c * HW + gy * WW + gx];
        s_in[c * 360 + iy * 20 + ix] = v;
    }

    const int ocg = tid >> 5;
    const int r   = tid & 31;
    const int ly  = r >> 1;
    const int lx0 = (r & 1) * 8;

    float* fout = g_featc + (size_t)b * 64 * HW;

    for (int chunk = 0; chunk < 2; chunk++) {
        const int oc_base = chunk * 32;
        __syncthreads();
        // coalesced weight staging: 576 rem x 32 oc
        for (int e = tid; e < 4608; e += 256) {
            int rem = e >> 3;
            int o4  = (e & 7) << 2;
            *(uint4*)(s_w + rem * 32 + o4) =
                *(const uint4*)(g_wt + rem * 64 + oc_base + o4);
        }
        __syncthreads();

        unsigned long long acc01[8], acc23[8];
        #pragma unroll
        for (int p = 0; p < 8; p++) { acc01[p] = 0ull; acc23[p] = 0ull; }

        for (int cin = 0; cin < 64; cin++) {
            const float* si  = s_in + cin * 360 + ly * 20 + lx0;
            const float* swc = s_w + cin * 9 * 32 + ocg * 4;
            #pragma unroll
            for (int ky = 0; ky < 3; ky++) {
                const float* row = si + ky * 20;
                float4 va = *(const float4*)(row);
                float4 vb = *(const float4*)(row + 4);
                float2 vc = *(const float2*)(row + 8);
                unsigned long long d[10];
                d[0]=dup2(va.x); d[1]=dup2(va.y); d[2]=dup2(va.z); d[3]=dup2(va.w);
                d[4]=dup2(vb.x); d[5]=dup2(vb.y); d[6]=dup2(vb.z); d[7]=dup2(vb.w);
                d[8]=dup2(vc.x); d[9]=dup2(vc.y);
                #pragma unroll
                for (int kx = 0; kx < 3; kx++) {
                    ulonglong2 wv = *(const ulonglong2*)(swc + (ky * 3 + kx) * 32);
                    #pragma unroll
                    for (int p = 0; p < 8; p++) {
                        acc01[p] = fma2(d[p + kx], wv.x, acc01[p]);
                        acc23[p] = fma2(d[p + kx], wv.y, acc23[p]);
                    }
                }
            }
        }

        float rr[4][8];
        #pragma unroll
        for (int p = 0; p < 8; p++) {
            float2 a = upk(acc01[p]);
            float2 c = upk(acc23[p]);
            rr[0][p] = a.x; rr[1][p] = a.y; rr[2][p] = c.x; rr[3][p] = c.y;
        }
        #pragma unroll
        for (int i = 0; i < 4; i++) {
            int oc = oc_base + ocg * 4 + i;
            float bias = b1[oc];
            float* op = fout + (size_t)oc * HW + (oy + ly) * WW + ox + lx0;
            float4 v0, v1;
            v0.x = fmaxf(rr[i][0] + bias, 0.f); v0.y = fmaxf(rr[i][1] + bias, 0.f);
            v0.z = fmaxf(rr[i][2] + bias, 0.f); v0.w = fmaxf(rr[i][3] + bias, 0.f);
            v1.x = fmaxf(rr[i][4] + bias, 0.f); v1.y = fmaxf(rr[i][5] + bias, 0.f);
            v1.z = fmaxf(rr[i][6] + bias, 0.f); v1.w = fmaxf(rr[i][7] + bias, 0.f);
            *(float4*)(op)     = v0;
            *(float4*)(op + 4) = v1;
        }
    }
}

// =====================================================================
// Kernel 2 (fused): 1x1 conv (64->80) + sigmoid + 3x3 peak + argmax.
// v2: 8x8 output tile, 10x10 halo (100 px), 128 threads -> ~4 blocks/SM.
// 4 groups of 20 classes; feat cached in regs as 32 channel-pairs.
// =====================================================================
__global__ __launch_bounds__(128, 4) void clspeak_kernel(
    const float* __restrict__ w2, const float* __restrict__ b2)
{
    __shared__ float s_w[80 * 64];
    __shared__ float s_b[80];
    __shared__ float s_cls[20 * 104];

    const int bx = blockIdx.x, by = blockIdx.y, b = blockIdx.z;
    const int ox = bx * 8, oy = by * 8;
    const int tid = threadIdx.x;
    const float NEG = -1e30f;

    for (int e = tid; e < 80 * 64; e += 128) s_w[e] = w2[e];
    if (tid < 80) s_b[tid] = b2[tid];

    unsigned long long fd[32];
    bool inimg = false;
    if (tid < 100) {
        int iy = tid / 10, ix = tid - iy * 10;
        int gy = oy + iy - 1, gx = ox + ix - 1;
        inimg = (gy >= 0 && gy < HH && gx >= 0 && gx < WW);
        const float* fp = g_featc + (size_t)b * 64 * HW + gy * WW + gx;
        #pragma unroll
        for (int i = 0; i < 32; i++) {
            float a = inimg ? fp[(2 * i) * HW]     : 0.f;
            float c = inimg ? fp[(2 * i + 1) * HW] : 0.f;
            fd[i] = pk2(a, c);
        }
    }
    __syncthreads();

    const int py = (tid >> 3) + 1, px = (tid & 7) + 1;
    const int pp = py * 10 + px;
    float best = -1.f;
    int cat = 0;

    for (int g = 0; g < 4; g++) {
        if (tid < 100) {
            #pragma unroll
            for (int cp = 0; cp < 10; cp++) {
                const int c0 = g * 20 + 2 * cp;
                unsigned long long a0 = 0ull, a1 = 0ull;
                const ulonglong2* w0 = (const ulonglong2*)(s_w + c0 * 64);
                const ulonglong2* w1 = (const ulonglong2*)(s_w + (c0 + 1) * 64);
                #pragma unroll
                for (int i = 0; i < 16; i++) {
                    ulonglong2 wa = w0[i];
                    ulonglong2 wb = w1[i];
                    a0 = fma2(fd[2 * i],     wa.x, a0);
                    a0 = fma2(fd[2 * i + 1], wa.y, a0);
                    a1 = fma2(fd[2 * i],     wb.x, a1);
                    a1 = fma2(fd[2 * i + 1], wb.y, a1);
                }
                float2 u0 = upk(a0), u1 = upk(a1);
                float v0 = u0.x + u0.y + s_b[c0];
                float v1 = u1.x + u1.y + s_b[c0 + 1];
                v0 = 1.f / (1.f + expf(-v0));
                v1 = 1.f / (1.f + expf(-v1));
                if (!inimg) { v0 = NEG; v1 = NEG; }
                s_cls[(2 * cp)     * 104 + tid] = v0;
                s_cls[(2 * cp + 1) * 104 + tid] = v1;
            }
        }
        __syncthreads();
        if (tid < 64) {
            #pragma unroll 4
            for (int c = 0; c < 20; c++) {
                const float* row = s_cls + c * 104;
                float v = row[pp];
                float m = v;
                m = fmaxf(m, row[pp - 11]); m = fmaxf(m, row[pp - 10]); m = fmaxf(m, row[pp - 9]);
                m = fmaxf(m, row[pp - 1]);                               m = fmaxf(m, row[pp + 1]);
                m = fmaxf(m, row[pp + 9]);  m = fmaxf(m, row[pp + 10]); m = fmaxf(m, row[pp + 11]);
                float k = (v == m) ? v : 0.f;
                if (k > best) { best = k; cat = g * 20 + c; }
            }
        }
        __syncthreads();
    }

    if (tid < 64) {
        int gp = (oy + py - 1) * WW + ox + px - 1;
        g_score[b * HW + gp] = best;
        g_cat[b * HW + gp]   = cat;
    }
}

// =====================================================================
// Kernel 3: top-100. Histogram radix threshold + compaction + rank-count.
// =====================================================================
#define TOPK_SMEM (8192 * 4 + 1024 * 4 + HW * 8)
__global__ __launch_bounds__(1024) void topk_kernel()
{
    extern __shared__ int smi[];
    int* hist = smi;
    int* suf  = smi + 8192;
    unsigned long long* cand = (unsigned long long*)(smi + 8192 + 1024);
    __shared__ int s_tstar, s_T, s_cnt;

    const int b = blockIdx.x;
    const int tid = threadIdx.x;
    const float* s = g_score + b * HW;

    for (int i = tid; i < 8192; i += 1024) hist[i] = 0;
    if (tid == 0) s_cnt = 0;
    __syncthreads();

    for (int j = tid; j < HW; j += 1024) {
        unsigned int u = __float_as_uint(s[j]);
        atomicAdd(&hist[u >> 19], 1);
    }
    __syncthreads();

    int seg = 0;
    #pragma unroll
    for (int k = 0; k < 8; k++) seg += hist[tid * 8 + k];
    suf[tid] = seg;
    __syncthreads();
    for (int off = 1; off < 1024; off <<= 1) {
        int v = suf[tid];
        int add = (tid + off < 1024) ? suf[tid + off] : 0;
        __syncthreads();
        suf[tid] = v + add;
        __syncthreads();
    }
    if (suf[tid] >= KTOP && (tid == 1023 || suf[tid + 1] < KTOP)) s_tstar = tid;
    __syncthreads();
    if (tid == s_tstar) {
        int acc = (tid == 1023) ? 0 : suf[tid + 1];
        for (int bb = tid * 8 + 7; bb >= tid * 8; bb--) {
            acc += hist[bb];
            if (acc >= KTOP) { s_T = bb; break; }
        }
    }
    __syncthreads();
    const int T = s_T;

    for (int j = tid; j < HW; j += 1024) {
        unsigned int u = __float_as_uint(s[j]);
        if ((int)(u >> 19) >= T) {
            int pos = atomicAdd(&s_cnt, 1);
            cand[pos] = ((unsigned long long)u << 32) | (unsigned long long)(HW - j);
        }
    }
    __syncthreads();
    const int N = s_cnt;

    for (int i = tid; i < N; i += 1024) {
        unsigned long long key = cand[i];
        int rank = 0;
        for (int j = 0; j < N; j++) rank += (cand[j] > key);
        if (rank < KTOP) {
            g_tscore[b * KTOP + rank] = __uint_as_float((unsigned int)(key >> 32));
            g_tind[b * KTOP + rank]   = HW - (int)(key & 0xFFFFFFFFull);
        }
    }
}

// =====================================================================
// Kernel 4: recompute reg/wh 3x3 conv at selected points + 1x1 heads +
// box decode. grid (50, B), 128 threads, 2 points/block.
// =====================================================================
#define PTS 2
__global__ __launch_bounds__(128) void point_kernel(
    const float* __restrict__ x,
    const float* __restrict__ rw1, const float* __restrict__ rb1,
    const float* __restrict__ rw2, const float* __restrict__ rb2,
    const float* __restrict__ ww1, const float* __restrict__ wb1,
    const float* __restrict__ ww2, const float* __restrict__ wb2)
{
    __shared__ float sx[PTS][576];
    __shared__ int   sp[PTS];
    __shared__ float sfa[128][PTS + 1];
    __shared__ float sres[PTS][4];

    const int g = blockIdx.x, b = blockIdx.y;
    const int tid = threadIdx.x;

    if (tid < PTS) sp[tid] = g_tind[b * KTOP + g * PTS + tid];
    __syncthreads();

    for (int e = tid; e < PTS * 576; e += 128) {
        int pt = e / 576;
        int r  = e - pt * 576;
        int c  = r / 9;
        int k9 = r - c * 9;
        int dy = k9 / 3 - 1, dx = k9 % 3 - 1;
        int p = sp[pt];
        int gy = (p >> 7) + dy, gx = (p & 127) + dx;
        float v = 0.f;
        if (gy >= 0 && gy < HH && gx >= 0 && gx < WW)
            v = x[((size_t)b * CINC + c) * HW + gy * WW + gx];
        sx[pt][r] = v;
    }
    __syncthreads();

    const float* wrow = (tid < 64) ? (rw1 + tid * 576) : (ww1 + (tid - 64) * 576);
    float bias = (tid < 64) ? rb1[tid] : wb1[tid - 64];
    float acc[PTS];
    #pragma unroll
    for (int pt = 0; pt < PTS; pt++) acc[pt] = bias;

    for (int j = 0; j < 576; j += 4) {
        float4 w4 = *(const float4*)(wrow + j);
        #pragma unroll
        for (int q = 0; q < 4; q++) {
            float w = (q == 0) ? w4.x : (q == 1) ? w4.y : (q == 2) ? w4.z : w4.w;
            #pragma unroll
            for (int pt = 0; pt < PTS; pt++)
                acc[pt] = fmaf(w, sx[pt][j + q], acc[pt]);
        }
    }
    #pragma unroll
    for (int pt = 0; pt < PTS; pt++) sfa[tid][pt] = fmaxf(acc[pt], 0.f);
    __syncthreads();

    if (tid < PTS * 4) {
        int pt = tid >> 2, o = tid & 3;
        float sv;
        if (o < 2) {
            sv = rb2[o];
            for (int i = 0; i < 64; i++) sv = fmaf(sfa[i][pt], rw2[o * 64 + i], sv);
            sv = 1.f / (1.f + expf(-sv));
        } else {
            int oo = o - 2;
            sv = wb2[oo];
            for (int i = 0; i < 64; i++) sv = fmaf(sfa[64 + i][pt], ww2[oo * 64 + i], sv);
            sv = expf(sv);
        }
        sres[pt][o] = sv;
    }
    __syncthreads();

    if (tid < PTS) {
        int p = sp[tid];
        float cx = (float)(p & 127) + sres[tid][0];
        float cy = (float)(p >> 7)  + sres[tid][1];
        float wv = sres[tid][2], hv = sres[tid][3];
        int k = b * KTOP + g * PTS + tid;
        g_boxes[k * 4 + 0] = (cx - wv * 0.5f) * 4.f;
        g_boxes[k * 4 + 1] = (cy - hv * 0.5f) * 4.f;
        g_boxes[k * 4 + 2] = (cx + wv * 0.5f) * 4.f;
        g_boxes[k * 4 + 3] = (cy + hv * 0.5f) * 4.f;
    }
}

// =====================================================================
// Kernel 5: greedy NMS + output assembly
// =====================================================================
__global__ __launch_bounds__(128) void nms_kernel(float* __restrict__ out)
{
    const int b = blockIdx.x;
    const int tid = threadIdx.x;
    __shared__ float bx[KTOP][4];
    __shared__ float barea[KTOP];
    __shared__ int keep[KTOP];

    float score = 0.f; int cat = 0;
    if (tid < KTOP) {
        int k = b * KTOP + tid;
        score = g_tscore[k];
        cat   = g_cat[b * HW + g_tind[k]];
        float x1 = g_boxes[k * 4 + 0], y1 = g_boxes[k * 4 + 1];
        float x2 = g_boxes[k * 4 + 2], y2 = g_boxes[k * 4 + 3];
        bx[tid][0] = x1; bx[tid][1] = y1; bx[tid][2] = x2; bx[tid][3] = y2;
        barea[tid] = (x2 - x1) * (y2 - y1);
        keep[tid] = (score > 0.2f) ? 1 : 0;
    }
    __syncthreads();

    for (int i = 0; i < KTOP - 1; i++) {
        if (tid < KTOP && tid > i && keep[i]) {
            float xx1 = fmaxf(bx[i][0], bx[tid][0]);
            float yy1 = fmaxf(bx[i][1], bx[tid][1]);
            float xx2 = fminf(bx[i][2], bx[tid][2]);
            float yy2 = fminf(bx[i][3], bx[tid][3]);
            float iw = fmaxf(xx2 - xx1, 0.f);
            float ih = fmaxf(yy2 - yy1, 0.f);
            float inter = iw * ih;
            float iou = inter / (barea[i] + barea[tid] - inter + 1e-9f);
            if (iou > 0.5f) keep[tid] = 0;
        }
        __syncthreads();
    }

    if (tid < KTOP) {
        int base = b * KTOP + tid;
        out[base * 4 + 0] = bx[tid][0];
        out[base * 4 + 1] = bx[tid][1];
        out[base * 4 + 2] = bx[tid][2];
        out[base * 4 + 3] = bx[tid][3];
        out[6400 + base] = (float)cat;
        out[8000 + base] = score;
        out[9600 + base] = keep[tid] ? 1.f : 0.f;
    }
}

// =====================================================================
extern "C" void kernel_launch(void* const* d_in, const int* in_sizes, int n_in,
                              void* d_out, int out_size)
{
    const float* x      = (const float*)d_in[0];
    const float* cls_w1 = (const float*)d_in[1];
    const float* cls_b1 = (const float*)d_in[2];
    const float* cls_w2 = (const float*)d_in[3];
    const float* cls_b2 = (const float*)d_in[4];
    const float* reg_w1 = (const float*)d_in[5];
    const float* reg_b1 = (const float*)d_in[6];
    const float* reg_w2 = (const float*)d_in[7];
    const float* reg_b2 = (const float*)d_in[8];
    const float* wh_w1  = (const float*)d_in[9];
    const float* wh_b1  = (const float*)d_in[10];
    const float* wh_w2  = (const float*)d_in[11];
    const float* wh_b2  = (const float*)d_in[12];
    float* out = (float*)d_out;

    cudaFuncSetAttribute(conv1_kernel, cudaFuncAttributeMaxDynamicSharedMemorySize, CONV1_SMEM);
    cudaFuncSetAttribute(topk_kernel, cudaFuncAttributeMaxDynamicSharedMemorySize, TOPK_SMEM);

    wprep_kernel<<<144, 256>>>(cls_w1);
    conv1_kernel<<<dim3(8, 8, BATCH), 256, CONV1_SMEM>>>(x, cls_b1);
    clspeak_kernel<<<dim3(16, 16, BATCH), 128>>>(cls_w2, cls_b2);
    topk_kernel<<<BATCH, 1024, TOPK_SMEM>>>();
    point_kernel<<<dim3(50, BATCH), 128>>>(x, reg_w1, reg_b1, reg_w2, reg_b2,
                                           wh_w1, wh_b1, wh_w2, wh_b2);
    nms_kernel<<<BATCH, 128>>>(out);
}

// round 12
// speedup vs baseline: 1.1487x; 1.0311x over previous
#include <cuda_runtime.h>
#include <cuda_fp16.h>
#include <math.h>
#include <stdint.h>

#define BATCH 16
#define CINC 64
#define HH 128
#define WW 128
#define HW 16384
#define NCLS 80
#define KTOP 100

// ---------------- device scratch ----------------
__device__ float g_featc[BATCH * 64 * HW];   // relu(conv3x3) cls branch
__device__ float g_score[BATCH * HW];
__device__ int   g_cat  [BATCH * HW];
__device__ float g_tscore[BATCH * KTOP];
__device__ int   g_tind  [BATCH * KTOP];
__device__ float g_boxes[BATCH * KTOP * 4];

// fp16 split input (x*16): [s in {0,1}][b*128+R][px*64+cin] (8192 elems/row)
#define XS_ELEMS_PER_SPLIT ((size_t)BATCH * 128 * 8192)
__device__ __half g_xs[2 * XS_ELEMS_PER_SPLIT];
// pre-swizzled fp16 split weights (w*64): [pass*9+tap][4096 elems, SW128]
__device__ __half g_wsw[18 * 4096];

#define SW128(o) ((o) ^ (((o) >> 3) & 0x70))
#define OUT_SCALE (1.f / 1024.f)

// ---------------- f32x2 helpers (clspeak) ----------------
__device__ __forceinline__ unsigned long long pk2(float lo, float hi) {
    unsigned long long r;
    asm("mov.b64 %0, {%1, %2};" : "=l"(r) : "r"(__float_as_uint(lo)), "r"(__float_as_uint(hi)));
    return r;
}
__device__ __forceinline__ unsigned long long fma2(unsigned long long a, unsigned long long b,
                                                   unsigned long long c) {
    unsigned long long d;
    asm("fma.rn.f32x2 %0, %1, %2, %3;" : "=l"(d) : "l"(a), "l"(b), "l"(c));
    return d;
}
__device__ __forceinline__ float2 upk(unsigned long long v) {
    unsigned int a, b;
    asm("mov.b64 {%0, %1}, %2;" : "=r"(a), "=r"(b) : "l"(v));
    return make_float2(__uint_as_float(a), __uint_as_float(b));
}

// ---------------- warp-mma helpers ----------------
__device__ __forceinline__ uint32_t smem_u32(const void* p) {
    uint32_t a;
    asm("{ .reg .u64 t; cvta.to.shared.u64 t, %1; cvt.u32.u64 %0, t; }" : "=r"(a) : "l"(p));
    return a;
}
__device__ __forceinline__ void ldsm_x4(uint32_t* r, uint32_t addr) {
    asm volatile("ldmatrix.sync.aligned.m8n8.x4.shared.b16 {%0,%1,%2,%3}, [%4];"
        : "=r"(r[0]), "=r"(r[1]), "=r"(r[2]), "=r"(r[3]) : "r"(addr));
}
__device__ __forceinline__ void mma16816(float* d, const uint32_t* a, const uint32_t* b) {
    asm volatile(
        "mma.sync.aligned.m16n8k16.row.col.f32.f16.f16.f32 "
        "{%0,%1,%2,%3}, {%4,%5,%6,%7}, {%8,%9}, {%0,%1,%2,%3};"
        : "+f"(d[0]), "+f"(d[1]), "+f"(d[2]), "+f"(d[3])
        : "r"(a[0]), "r"(a[1]), "r"(a[2]), "r"(a[3]), "r"(b[0]), "r"(b[1]));
}

// =====================================================================
// Prep 1: split x*16 into 2 fp16 parts, layout [s][b*128+R][px*64+cin]
// =====================================================================
__global__ __launch_bounds__(256) void xsplit_kernel(const float* __restrict__ x)
{
    __shared__ float tile[64 * 128];
    const int R = blockIdx.x, b = blockIdx.y;
    const int tid = threadIdx.x;

    for (int e = tid; e < 8192; e += 256) {
        int cin = e >> 7, px = e & 127;
        tile[e] = x[((size_t)(b * 64 + cin) * 128 + R) * 128 + px];
    }
    __syncthreads();

    const size_t rowbase = ((size_t)b * 128 + R) * 8192;
    for (int e = tid; e < 4096; e += 256) {
        int e2 = e * 2;
        int px = e2 >> 6, cin0 = e2 & 63;
        float f0 = tile[cin0 * 128 + px] * 16.f;
        float f1 = tile[(cin0 + 1) * 128 + px] * 16.f;
        __half h10 = __float2half_rn(f0);
        __half h11 = __float2half_rn(f1);
        __half h20 = __float2half_rn(f0 - __half2float(h10));
        __half h21 = __float2half_rn(f1 - __half2float(h11));
        size_t eb = rowbase + e2;
        g_xs[eb] = h10; g_xs[eb + 1] = h11;
        g_xs[XS_ELEMS_PER_SPLIT + eb]     = h20;
        g_xs[XS_ELEMS_PER_SPLIT + eb + 1] = h21;
    }
}

// =====================================================================
// Prep 2: split + pre-swizzle weights (w*64): g_wsw[pass*9+tap]
// =====================================================================
__global__ __launch_bounds__(256) void wprep_kernel(const float* __restrict__ w1)
{
    const int t = blockIdx.x;          // 0..17 = pass*9 + tap
    const int pass = t / 9, tap = t - pass * 9;
    const int tid = threadIdx.x;
    for (int e = tid; e < 4096; e += 256) {
        int oc = e >> 6, cin = e & 63;
        float f = w1[oc * 576 + cin * 9 + tap] * 64.f;
        __half h1 = __float2half_rn(f);
        __half out = pass ? __float2half_rn(f - __half2float(h1)) : h1;
        uint32_t o = SW128((uint32_t)e * 2);
        g_wsw[(size_t)t * 4096 + (o >> 1)] = out;
    }
}

// =====================================================================
// conv via warp-level mma.sync (fp16, 4-term = (x1+x2)(w1+w2)), 2 passes.
// CTA = (rowgroup of 8, batch), 256 threads (8 warps, 16 px each).
// A: 3-slot ring of 130-row tiles (row = px+1; kx via +row offset), 2 splits.
// B: 9 pre-swizzled tap tiles (w1 pass0, w2 pass1).
// =====================================================================
#define BT_OFF 0u
#define AT_OFF 73728u
#define SLOT_STRIDE 33792u
#define SPLIT_STRIDE 16896u
#define CONVM_SMEM 175104

__device__ __forceinline__ void ld_a_row(uint4* pf, int b, int R, int tid) {
    #pragma unroll
    for (int j = 0; j < 9; j++) {
        int c = j * 256 + tid;
        uint4 v = make_uint4(0, 0, 0, 0);
        if (c < 2080) {
            int s = (c >= 1040) ? 1 : 0;
            int r = c - s * 1040;
            int px_dst = r >> 3;
            int w16 = (r & 7) * 16;
            int px_src = px_dst - 1;
            if (R >= 0 && R < 128 && px_src >= 0 && px_src < 128) {
                const char* src = (const char*)g_xs
                    + (size_t)s * XS_ELEMS_PER_SPLIT * 2
                    + (((size_t)b * 128 + R) * 8192 + (size_t)px_src * 64) * 2 + w16;
                v = __ldg((const uint4*)src);
            }
        }
        pf[j] = v;
    }
}
__device__ __forceinline__ void st_a_row(const uint4* pf, char* smem, int slot, int tid) {
    #pragma unroll
    for (int j = 0; j < 9; j++) {
        int c = j * 256 + tid;
        if (c < 2080) {
            int s = (c >= 1040) ? 1 : 0;
            int r = c - s * 1040;
            uint32_t o = ((uint32_t)(r >> 3)) * 128 + (uint32_t)(r & 7) * 16;
            *(uint4*)(smem + AT_OFF + slot * SLOT_STRIDE + s * SPLIT_STRIDE + SW128(o)) = pf[j];
        }
    }
}

template<int PASS>
__global__ __launch_bounds__(256, 1) void conv_mma_kernel(const float* __restrict__ b1)
{
    extern __shared__ char smem[];
    const uint32_t sb = smem_u32(smem);
    const int g = blockIdx.x, b = blockIdx.y;
    const int tid = threadIdx.x;
    const int w = tid >> 5, lane = tid & 31;
    const int Y0 = g * 8;
    const int q = lane >> 3, rr = lane & 7;

    const uint32_t a_row = (uint32_t)(w * 16 + rr + 8 * (q & 1));  // tile row = px + kx
    const uint32_t a_sub = (uint32_t)(16 * (q >> 1));
    const uint32_t b_base = (uint32_t)((8 * (q >> 1) + rr) * 128 + 16 * (q & 1));
    const int px0 = w * 16 + (lane >> 2);
    const int oc0 = 2 * (lane & 3);
    float* gout = g_featc + (size_t)b * 64 * HW;

    // stage B tiles (pre-swizzled -> pure copy): 9 x 8192 B
    for (int idx = tid; idx < 4608; idx += 256) {
        *(uint4*)(smem + BT_OFF + (uint32_t)idx * 16) =
            __ldg((const uint4*)((const char*)g_wsw + (size_t)PASS * 9 * 8192 + (size_t)idx * 16));
    }
    // prologue: stage input rows Y0-1, Y0, Y0+1 (slot = (R+1)%3)
    {
        uint4 pf0[9];
        for (int R = Y0 - 1; R <= Y0 + 1; R++) {
            ld_a_row(pf0, b, R, tid);
            st_a_row(pf0, smem, (R + 1) % 3, tid);
        }
    }
    __syncthreads();

    for (int r0 = 0; r0 < 8; r0++) {
        const int y = Y0 + r0;
        uint4 pf[9];
        if (r0 < 7) ld_a_row(pf, b, y + 2, tid);

        float acc[8][4];
        #pragma unroll
        for (int i = 0; i < 8; i++)
            #pragma unroll
            for (int j = 0; j < 4; j++) acc[i][j] = 0.f;

        #pragma unroll
        for (int ky = 0; ky < 3; ky++) {
            const uint32_t slotb = sb + AT_OFF + (uint32_t)(((y + ky) % 3) * SLOT_STRIDE);
            #pragma unroll
            for (int kc = 0; kc < 4; kc++) {
                uint32_t a1f[3][4], a2f[3][4];
                #pragma unroll
                for (int kx = 0; kx < 3; kx++) {
                    uint32_t o = (a_row + kx) * 128 + a_sub + 32 * kc;
                    ldsm_x4(a1f[kx], slotb + SW128(o));
                    ldsm_x4(a2f[kx], slotb + SPLIT_STRIDE + SW128(o));
                }
                #pragma unroll
                for (int kx = 0; kx < 3; kx++) {
                    const uint32_t tile = sb + BT_OFF + (uint32_t)((ky * 3 + kx) * 8192);
                    #pragma unroll
                    for (int nt2 = 0; nt2 < 4; nt2++) {
                        uint32_t bb[4];
                        ldsm_x4(bb, tile + SW128(b_base + nt2 * 2048u + 32 * kc));
                        mma16816(acc[nt2 * 2],     a1f[kx], bb);
                        mma16816(acc[nt2 * 2 + 1], a1f[kx], bb + 2);
                        mma16816(acc[nt2 * 2],     a2f[kx], bb);
                        mma16816(acc[nt2 * 2 + 1], a2f[kx], bb + 2);
                    }
                }
            }
        }

        // epilogue (results carry 1024x scale)
        #pragma unroll
        for (int nt = 0; nt < 8; nt++) {
            const int oc = nt * 8 + oc0;
            float* p0 = gout + (size_t)oc * HW + y * 128 + px0;
            float* p1 = p0 + HW;
            if (PASS == 0) {
                p0[0] = acc[nt][0]; p1[0] = acc[nt][1];
                p0[8] = acc[nt][2]; p1[8] = acc[nt][3];
            } else {
                const float ba = __ldg(b1 + oc), bbv = __ldg(b1 + oc + 1);
                p0[0] = fmaxf((p0[0] + acc[nt][0]) * OUT_SCALE + ba,  0.f);
                p1[0] = fmaxf((p1[0] + acc[nt][1]) * OUT_SCALE + bbv, 0.f);
                p0[8] = fmaxf((p0[8] + acc[nt][2]) * OUT_SCALE + ba,  0.f);
                p1[8] = fmaxf((p1[8] + acc[nt][3]) * OUT_SCALE + bbv, 0.f);
            }
        }
        __syncthreads();
        if (r0 < 7) st_a_row(pf, smem, (y + 3) % 3, tid);
        __syncthreads();
    }
}

// =====================================================================
// Fused 1x1 conv (64->80) + sigmoid + 3x3 peak + argmax
// =====================================================================
__global__ __launch_bounds__(128, 4) void clspeak_kernel(
    const float* __restrict__ w2, const float* __restrict__ b2)
{
    __shared__ float s_w[80 * 64];
    __shared__ float s_b[80];
    __shared__ float s_cls[20 * 104];

    const int bx = blockIdx.x, by = blockIdx.y, b = blockIdx.z;
    const int ox = bx * 8, oy = by * 8;
    const int tid = threadIdx.x;
    const float NEG = -1e30f;

    for (int e = tid; e < 80 * 64; e += 128) s_w[e] = w2[e];
    if (tid < 80) s_b[tid] = b2[tid];

    unsigned long long fd[32];
    bool inimg = false;
    if (tid < 100) {
        int iy = tid / 10, ix = tid - iy * 10;
        int gy = oy + iy - 1, gx = ox + ix - 1;
        inimg = (gy >= 0 && gy < HH && gx >= 0 && gx < WW);
        const float* fp = g_featc + (size_t)b * 64 * HW + gy * WW + gx;
        #pragma unroll
        for (int i = 0; i < 32; i++) {
            float a = inimg ? fp[(2 * i) * HW]     : 0.f;
            float c = inimg ? fp[(2 * i + 1) * HW] : 0.f;
            fd[i] = pk2(a, c);
        }
    }
    __syncthreads();

    const int py = (tid >> 3) + 1, px = (tid & 7) + 1;
    const int pp = py * 10 + px;
    float best = -1.f;
    int cat = 0;

    for (int g = 0; g < 4; g++) {
        if (tid < 100) {
            #pragma unroll
            for (int cp = 0; cp < 10; cp++) {
                const int c0 = g * 20 + 2 * cp;
                unsigned long long a0 = 0ull, a1 = 0ull;
                const ulonglong2* w0 = (const ulonglong2*)(s_w + c0 * 64);
                const ulonglong2* w1 = (const ulonglong2*)(s_w + (c0 + 1) * 64);
                #pragma unroll
                for (int i = 0; i < 16; i++) {
                    ulonglong2 wa = w0[i];
                    ulonglong2 wb = w1[i];
                    a0 = fma2(fd[2 * i],     wa.x, a0);
                    a0 = fma2(fd[2 * i + 1], wa.y, a0);
                    a1 = fma2(fd[2 * i],     wb.x, a1);
                    a1 = fma2(fd[2 * i + 1], wb.y, a1);
                }
                float2 u0 = upk(a0), u1 = upk(a1);
                float v0 = u0.x + u0.y + s_b[c0];
                float v1 = u1.x + u1.y + s_b[c0 + 1];
                v0 = 1.f / (1.f + expf(-v0));
                v1 = 1.f / (1.f + expf(-v1));
                if (!inimg) { v0 = NEG; v1 = NEG; }
                s_cls[(2 * cp)     * 104 + tid] = v0;
                s_cls[(2 * cp + 1) * 104 + tid] = v1;
            }
        }
        __syncthreads();
        if (tid < 64) {
            #pragma unroll 4
            for (int c = 0; c < 20; c++) {
                const float* row = s_cls + c * 104;
                float v = row[pp];
                float m = v;
                m = fmaxf(m, row[pp - 11]); m = fmaxf(m, row[pp - 10]); m = fmaxf(m, row[pp - 9]);
                m = fmaxf(m, row[pp - 1]);                               m = fmaxf(m, row[pp + 1]);
                m = fmaxf(m, row[pp + 9]);  m = fmaxf(m, row[pp + 10]); m = fmaxf(m, row[pp + 11]);
                float k = (v == m) ? v : 0.f;
                if (k > best) { best = k; cat = g * 20 + c; }
            }
        }
        __syncthreads();
    }

    if (tid < 64) {
        int gp = (oy + py - 1) * WW + ox + px - 1;
        g_score[b * HW + gp] = best;
        g_cat[b * HW + gp]   = cat;
    }
}

// =====================================================================
// top-100
// =====================================================================
#define TOPK_SMEM (8192 * 4 + 1024 * 4 + HW * 8)
__global__ __launch_bounds__(1024) void topk_kernel()
{
    extern __shared__ int smi[];
    int* hist = smi;
    int* suf  = smi + 8192;
    unsigned long long* cand = (unsigned long long*)(smi + 8192 + 1024);
    __shared__ int s_tstar, s_T, s_cnt;

    const int b = blockIdx.x;
    const int tid = threadIdx.x;
    const float* s = g_score + b * HW;

    for (int i = tid; i < 8192; i += 1024) hist[i] = 0;
    if (tid == 0) s_cnt = 0;
    __syncthreads();

    for (int j = tid; j < HW; j += 1024) {
        unsigned int u = __float_as_uint(s[j]);
        atomicAdd(&hist[u >> 19], 1);
    }
    __syncthreads();

    int seg = 0;
    #pragma unroll
    for (int k = 0; k < 8; k++) seg += hist[tid * 8 + k];
    suf[tid] = seg;
    __syncthreads();
    for (int off = 1; off < 1024; off <<= 1) {
        int v = suf[tid];
        int add = (tid + off < 1024) ? suf[tid + off] : 0;
        __syncthreads();
        suf[tid] = v + add;
        __syncthreads();
    }
    if (suf[tid] >= KTOP && (tid == 1023 || suf[tid + 1] < KTOP)) s_tstar = tid;
    __syncthreads();
    if (tid == s_tstar) {
        int acc = (tid == 1023) ? 0 : suf[tid + 1];
        for (int bb = tid * 8 + 7; bb >= tid * 8; bb--) {
            acc += hist[bb];
            if (acc >= KTOP) { s_T = bb; break; }
        }
    }
    __syncthreads();
    const int T = s_T;

    for (int j = tid; j < HW; j += 1024) {
        unsigned int u = __float_as_uint(s[j]);
        if ((int)(u >> 19) >= T) {
            int pos = atomicAdd(&s_cnt, 1);
            cand[pos] = ((unsigned long long)u << 32) | (unsigned long long)(HW - j);
        }
    }
    __syncthreads();
    const int N = s_cnt;

    for (int i = tid; i < N; i += 1024) {
        unsigned long long key = cand[i];
        int rank = 0;
        for (int j = 0; j < N; j++) rank += (cand[j] > key);
        if (rank < KTOP) {
            g_tscore[b * KTOP + rank] = __uint_as_float((unsigned int)(key >> 32));
            g_tind[b * KTOP + rank]   = HW - (int)(key & 0xFFFFFFFFull);
        }
    }
}

// =====================================================================
// reg/wh at selected points (PTS=2)
// =====================================================================
#define PTS 2
__global__ __launch_bounds__(128) void point_kernel(
    const float* __restrict__ x,
    const float* __restrict__ rw1, const float* __restrict__ rb1,
    const float* __restrict__ rw2, const float* __restrict__ rb2,
    const float* __restrict__ ww1, const float* __restrict__ wb1,
    const float* __restrict__ ww2, const float* __restrict__ wb2)
{
    __shared__ float sx[PTS][576];
    __shared__ int   sp[PTS];
    __shared__ float sfa[128][PTS + 1];
    __shared__ float sres[PTS][4];

    const int g = blockIdx.x, b = blockIdx.y;
    const int tid = threadIdx.x;

    if (tid < PTS) sp[tid] = g_tind[b * KTOP + g * PTS + tid];
    __syncthreads();

    for (int e = tid; e < PTS * 576; e += 128) {
        int pt = e / 576;
        int r  = e - pt * 576;
        int c  = r / 9;
        int k9 = r - c * 9;
        int dy = k9 / 3 - 1, dx = k9 % 3 - 1;
        int p = sp[pt];
        int gy = (p >> 7) + dy, gx = (p & 127) + dx;
        float v = 0.f;
        if (gy >= 0 && gy < HH && gx >= 0 && gx < WW)
            v = x[((size_t)b * CINC + c) * HW + gy * WW + gx];
        sx[pt][r] = v;
    }
    __syncthreads();

    const float* wrow = (tid < 64) ? (rw1 + tid * 576) : (ww1 + (tid - 64) * 576);
    float bias = (tid < 64) ? rb1[tid] : wb1[tid - 64];
    float acc[PTS];
    #pragma unroll
    for (int pt = 0; pt < PTS; pt++) acc[pt] = bias;

    for (int j = 0; j < 576; j += 4) {
        float4 w4 = *(const float4*)(wrow + j);
        #pragma unroll
        for (int q = 0; q < 4; q++) {
            float w = (q == 0) ? w4.x : (q == 1) ? w4.y : (q == 2) ? w4.z : w4.w;
            #pragma unroll
            for (int pt = 0; pt < PTS; pt++)
                acc[pt] = fmaf(w, sx[pt][j + q], acc[pt]);
        }
    }
    #pragma unroll
    for (int pt = 0; pt < PTS; pt++) sfa[tid][pt] = fmaxf(acc[pt], 0.f);
    __syncthreads();

    if (tid < PTS * 4) {
        int pt = tid >> 2, o = tid & 3;
        float sv;
        if (o < 2) {
            sv = rb2[o];
            for (int i = 0; i < 64; i++) sv = fmaf(sfa[i][pt], rw2[o * 64 + i], sv);
            sv = 1.f / (1.f + expf(-sv));
        } else {
            int oo = o - 2;
            sv = wb2[oo];
            for (int i = 0; i < 64; i++) sv = fmaf(sfa[64 + i][pt], ww2[oo * 64 + i], sv);
            sv = expf(sv);
        }
        sres[pt][o] = sv;
    }
    __syncthreads();

    if (tid < PTS) {
        int p = sp[tid];
        float cx = (float)(p & 127) + sres[tid][0];
        float cy = (float)(p >> 7)  + sres[tid][1];
        float wv = sres[tid][2], hv = sres[tid][3];
        int k = b * KTOP + g * PTS + tid;
        g_boxes[k * 4 + 0] = (cx - wv * 0.5f) * 4.f;
        g_boxes[k * 4 + 1] = (cy - hv * 0.5f) * 4.f;
        g_boxes[k * 4 + 2] = (cx + wv * 0.5f) * 4.f;
        g_boxes[k * 4 + 3] = (cy + hv * 0.5f) * 4.f;
    }
}

// =====================================================================
// NMS + output
// =====================================================================
__global__ __launch_bounds__(128) void nms_kernel(float* __restrict__ out)
{
    const int b = blockIdx.x;
    const int tid = threadIdx.x;
    __shared__ float bx[KTOP][4];
    __shared__ float barea[KTOP];
    __shared__ int keep[KTOP];

    float score = 0.f; int cat = 0;
    if (tid < KTOP) {
        int k = b * KTOP + tid;
        score = g_tscore[k];
        cat   = g_cat[b * HW + g_tind[k]];
        float x1 = g_boxes[k * 4 + 0], y1 = g_boxes[k * 4 + 1];
        float x2 = g_boxes[k * 4 + 2], y2 = g_boxes[k * 4 + 3];
        bx[tid][0] = x1; bx[tid][1] = y1; bx[tid][2] = x2; bx[tid][3] = y2;
        barea[tid] = (x2 - x1) * (y2 - y1);
        keep[tid] = (score > 0.2f) ? 1 : 0;
    }
    __syncthreads();

    for (int i = 0; i < KTOP - 1; i++) {
        if (tid < KTOP && tid > i && keep[i]) {
            float xx1 = fmaxf(bx[i][0], bx[tid][0]);
            float yy1 = fmaxf(bx[i][1], bx[tid][1]);
            float xx2 = fminf(bx[i][2], bx[tid][2]);
            float yy2 = fminf(bx[i][3], bx[tid][3]);
            float iw = fmaxf(xx2 - xx1, 0.f);
            float ih = fmaxf(yy2 - yy1, 0.f);
            float inter = iw * ih;
            float iou = inter / (barea[i] + barea[tid] - inter + 1e-9f);
            if (iou > 0.5f) keep[tid] = 0;
        }
        __syncthreads();
    }

    if (tid < KTOP) {
        int base = b * KTOP + tid;
        out[base * 4 + 0] = bx[tid][0];
        out[base * 4 + 1] = bx[tid][1];
        out[base * 4 + 2] = bx[tid][2];
        out[base * 4 + 3] = bx[tid][3];
        out[6400 + base] = (float)cat;
        out[8000 + base] = score;
        out[9600 + base] = keep[tid] ? 1.f : 0.f;
    }
}

// =====================================================================
extern "C" void kernel_launch(void* const* d_in, const int* in_sizes, int n_in,
                              void* d_out, int out_size)
{
    const float* x      = (const float*)d_in[0];
    const float* cls_w1 = (const float*)d_in[1];
    const float* cls_b1 = (const float*)d_in[2];
    const float* cls_w2 = (const float*)d_in[3];
    const float* cls_b2 = (const float*)d_in[4];
    const float* reg_w1 = (const float*)d_in[5];
    const float* reg_b1 = (const float*)d_in[6];
    const float* reg_w2 = (const float*)d_in[7];
    const float* reg_b2 = (const float*)d_in[8];
    const float* wh_w1  = (const float*)d_in[9];
    const float* wh_b1  = (const float*)d_in[10];
    const float* wh_w2  = (const float*)d_in[11];
    const float* wh_b2  = (const float*)d_in[12];
    float* out = (float*)d_out;

    cudaFuncSetAttribute(conv_mma_kernel<0>, cudaFuncAttributeMaxDynamicSharedMemorySize, CONVM_SMEM);
    cudaFuncSetAttribute(conv_mma_kernel<1>, cudaFuncAttributeMaxDynamicSharedMemorySize, CONVM_SMEM);
    cudaFuncSetAttribute(topk_kernel, cudaFuncAttributeMaxDynamicSharedMemorySize, TOPK_SMEM);

    xsplit_kernel<<<dim3(128, BATCH), 256>>>(x);
    wprep_kernel<<<18, 256>>>(cls_w1);
    conv_mma_kernel<0><<<dim3(16, BATCH), 256, CONVM_SMEM>>>(cls_b1);
    conv_mma_kernel<1><<<dim3(16, BATCH), 256, CONVM_SMEM>>>(cls_b1);
    clspeak_kernel<<<dim3(16, 16, BATCH), 128>>>(cls_w2, cls_b2);
    topk_kernel<<<BATCH, 1024, TOPK_SMEM>>>();
    point_kernel<<<dim3(50, BATCH), 128>>>(x, reg_w1, reg_b1, reg_w2, reg_b2,
                                           wh_w1, wh_b1, wh_w2, wh_b2);
    nms_kernel<<<BATCH, 128>>>(out);
}

// round 13
// speedup vs baseline: 1.1553x; 1.0057x over previous
#include <cuda_runtime.h>
#include <cuda_fp16.h>
#include <math.h>
#include <stdint.h>

#define BATCH 16
#define CINC 64
#define HH 128
#define WW 128
#define HW 16384
#define NCLS 80
#define KTOP 100

// ---------------- device scratch ----------------
__device__ float g_featc[BATCH * 64 * HW];   // relu(conv3x3) cls branch
__device__ float g_score[BATCH * HW];
__device__ int   g_cat  [BATCH * HW];
__device__ float g_tscore[BATCH * KTOP];
__device__ int   g_tind  [BATCH * KTOP];
__device__ float g_boxes[BATCH * KTOP * 4];

// fp16 split input (x*16): [s in {0,1}][b*128+R][px*64+cin] (8192 elems/row)
#define XS_ELEMS_PER_SPLIT ((size_t)BATCH * 128 * 8192)
__device__ __half g_xs[2 * XS_ELEMS_PER_SPLIT];
// pre-swizzled fp16 split weights (w*64): [pass*9+tap][4096 elems, SW128]
__device__ __half g_wsw[18 * 4096];

#define SW128(o) ((o) ^ (((o) >> 3) & 0x70))
#define OUT_SCALE (1.f / 1024.f)

// ---------------- f32x2 helpers (clspeak) ----------------
__device__ __forceinline__ unsigned long long pk2(float lo, float hi) {
    unsigned long long r;
    asm("mov.b64 %0, {%1, %2};" : "=l"(r) : "r"(__float_as_uint(lo)), "r"(__float_as_uint(hi)));
    return r;
}
__device__ __forceinline__ unsigned long long fma2(unsigned long long a, unsigned long long b,
                                                   unsigned long long c) {
    unsigned long long d;
    asm("fma.rn.f32x2 %0, %1, %2, %3;" : "=l"(d) : "l"(a), "l"(b), "l"(c));
    return d;
}
__device__ __forceinline__ float2 upk(unsigned long long v) {
    unsigned int a, b;
    asm("mov.b64 {%0, %1}, %2;" : "=r"(a), "=r"(b) : "l"(v));
    return make_float2(__uint_as_float(a), __uint_as_float(b));
}

// ---------------- warp-mma / cp.async helpers ----------------
__device__ __forceinline__ uint32_t smem_u32(const void* p) {
    uint32_t a;
    asm("{ .reg .u64 t; cvta.to.shared.u64 t, %1; cvt.u32.u64 %0, t; }" : "=r"(a) : "l"(p));
    return a;
}
__device__ __forceinline__ void ldsm_x4(uint32_t* r, uint32_t addr) {
    asm volatile("ldmatrix.sync.aligned.m8n8.x4.shared.b16 {%0,%1,%2,%3}, [%4];"
        : "=r"(r[0]), "=r"(r[1]), "=r"(r[2]), "=r"(r[3]) : "r"(addr));
}
__device__ __forceinline__ void mma16816(float* d, const uint32_t* a, const uint32_t* b) {
    asm volatile(
        "mma.sync.aligned.m16n8k16.row.col.f32.f16.f16.f32 "
        "{%0,%1,%2,%3}, {%4,%5,%6,%7}, {%8,%9}, {%0,%1,%2,%3};"
        : "+f"(d[0]), "+f"(d[1]), "+f"(d[2]), "+f"(d[3])
        : "r"(a[0]), "r"(a[1]), "r"(a[2]), "r"(a[3]), "r"(b[0]), "r"(b[1]));
}
__device__ __forceinline__ void cp_async16(uint32_t dst, const void* src, bool valid) {
    int sz = valid ? 16 : 0;
    asm volatile("cp.async.cg.shared.global [%0], [%1], 16, %2;"
                 :: "r"(dst), "l"(src), "r"(sz) : "memory");
}
__device__ __forceinline__ void cp_commit() {
    asm volatile("cp.async.commit_group;" ::: "memory");
}
__device__ __forceinline__ void cp_wait_all() {
    asm volatile("cp.async.wait_group 0;" ::: "memory");
}

// =====================================================================
// Prep 1: split x*16 into 2 fp16 parts, layout [s][b*128+R][px*64+cin]
// =====================================================================
__global__ __launch_bounds__(256) void xsplit_kernel(const float* __restrict__ x)
{
    __shared__ float tile[64 * 128];
    const int R = blockIdx.x, b = blockIdx.y;
    const int tid = threadIdx.x;

    for (int e = tid; e < 8192; e += 256) {
        int cin = e >> 7, px = e & 127;
        tile[e] = x[((size_t)(b * 64 + cin) * 128 + R) * 128 + px];
    }
    __syncthreads();

    const size_t rowbase = ((size_t)b * 128 + R) * 8192;
    for (int e = tid; e < 4096; e += 256) {
        int e2 = e * 2;
        int px = e2 >> 6, cin0 = e2 & 63;
        float f0 = tile[cin0 * 128 + px] * 16.f;
        float f1 = tile[(cin0 + 1) * 128 + px] * 16.f;
        __half h10 = __float2half_rn(f0);
        __half h11 = __float2half_rn(f1);
        __half h20 = __float2half_rn(f0 - __half2float(h10));
        __half h21 = __float2half_rn(f1 - __half2float(h11));
        size_t eb = rowbase + e2;
        g_xs[eb] = h10; g_xs[eb + 1] = h11;
        g_xs[XS_ELEMS_PER_SPLIT + eb]     = h20;
        g_xs[XS_ELEMS_PER_SPLIT + eb + 1] = h21;
    }
}

// =====================================================================
// Prep 2: split + pre-swizzle weights (w*64): g_wsw[pass*9+tap]
// =====================================================================
__global__ __launch_bounds__(256) void wprep_kernel(const float* __restrict__ w1)
{
    const int t = blockIdx.x;          // 0..17 = pass*9 + tap
    const int pass = t / 9, tap = t - pass * 9;
    const int tid = threadIdx.x;
    for (int e = tid; e < 4096; e += 256) {
        int oc = e >> 6, cin = e & 63;
        float f = w1[oc * 576 + cin * 9 + tap] * 64.f;
        __half h1 = __float2half_rn(f);
        __half out = pass ? __float2half_rn(f - __half2float(h1)) : h1;
        uint32_t o = SW128((uint32_t)e * 2);
        g_wsw[(size_t)t * 4096 + (o >> 1)] = out;
    }
}

// =====================================================================
// conv via warp-level mma.sync (fp16, 4-term), 2 passes, cp.async staging.
// CTA = (rowgroup of 8, batch), 256 threads (8 warps, 16 px each).
// A: 4-slot ring of 130-row tiles staged by cp.async (zfill boundaries).
// B: 9 pre-swizzled tap tiles.
// =====================================================================
#define BT_OFF 0u
#define AT_OFF 73728u
#define SLOT_STRIDE 33792u
#define SPLIT_STRIDE 16896u
#define CONVM_SMEM (73728 + 4 * 33792)

// stage one input row (2 splits x 130 px x 128B) into ring slot via cp.async
__device__ __forceinline__ void cp_a_row(char* smem, int b, int R, int slot, int tid) {
    #pragma unroll
    for (int j = 0; j < 9; j++) {
        int c = j * 256 + tid;
        if (c < 2080) {
            int s = (c >= 1040) ? 1 : 0;
            int r = c - s * 1040;
            int px_dst = r >> 3;
            int w16 = (r & 7) * 16;
            int px_src = px_dst - 1;
            bool valid = (R >= 0 && R < 128 && px_src >= 0 && px_src < 128);
            const char* src = (const char*)g_xs
                + (size_t)s * XS_ELEMS_PER_SPLIT * 2
                + (valid ? ((((size_t)b * 128 + R) * 8192 + (size_t)px_src * 64) * 2 + w16) : 0);
            uint32_t o = ((uint32_t)px_dst) * 128 + (uint32_t)w16;
            uint32_t dst = smem_u32(smem + AT_OFF + slot * SLOT_STRIDE
                                    + s * SPLIT_STRIDE + SW128(o));
            cp_async16(dst, src, valid);
        }
    }
}

template<int PASS>
__global__ __launch_bounds__(256, 1) void conv_mma_kernel(const float* __restrict__ b1)
{
    extern __shared__ char smem[];
    const uint32_t sb = smem_u32(smem);
    const int g = blockIdx.x, b = blockIdx.y;
    const int tid = threadIdx.x;
    const int w = tid >> 5, lane = tid & 31;
    const int Y0 = g * 8;
    const int q = lane >> 3, rr = lane & 7;

    const uint32_t a_row = (uint32_t)(w * 16 + rr + 8 * (q & 1));  // tile row = px + kx
    const uint32_t a_sub = (uint32_t)(16 * (q >> 1));
    const uint32_t b_base = (uint32_t)((8 * (q >> 1) + rr) * 128 + 16 * (q & 1));
    const int px0 = w * 16 + (lane >> 2);
    const int oc0 = 2 * (lane & 3);
    float* gout = g_featc + (size_t)b * 64 * HW;

    // stage B tiles (pre-swizzled -> pure copy): 9 x 8192 B
    for (int idx = tid; idx < 4608; idx += 256) {
        *(uint4*)(smem + BT_OFF + (uint32_t)idx * 16) =
            __ldg((const uint4*)((const char*)g_wsw + (size_t)PASS * 9 * 8192 + (size_t)idx * 16));
    }
    // prologue: stage rows Y0-1, Y0, Y0+1 into slots (R+1)&3
    for (int R = Y0 - 1; R <= Y0 + 1; R++) {
        cp_a_row(smem, b, R, (R + 1) & 3, tid);
    }
    cp_commit();
    cp_wait_all();
    __syncthreads();

    for (int r0 = 0; r0 < 8; r0++) {
        const int y = Y0 + r0;
        // prefetch row y+2 into the free slot (y+3)&3; overlaps with compute
        if (r0 < 7) {
            cp_a_row(smem, b, y + 2, (y + 3) & 3, tid);
            cp_commit();
        }

        float acc[8][4];
        #pragma unroll
        for (int i = 0; i < 8; i++)
            #pragma unroll
            for (int j = 0; j < 4; j++) acc[i][j] = 0.f;

        #pragma unroll
        for (int ky = 0; ky < 3; ky++) {
            const uint32_t slotb = sb + AT_OFF + (uint32_t)(((y + ky) & 3) * SLOT_STRIDE);
            #pragma unroll
            for (int kc = 0; kc < 4; kc++) {
                #pragma unroll
                for (int kx = 0; kx < 3; kx++) {
                    uint32_t o = (a_row + kx) * 128 + a_sub + 32 * kc;
                    uint32_t a1f[4], a2f[4];
                    ldsm_x4(a1f, slotb + SW128(o));
                    ldsm_x4(a2f, slotb + SPLIT_STRIDE + SW128(o));
                    const uint32_t tile = sb + BT_OFF + (uint32_t)((ky * 3 + kx) * 8192);
                    #pragma unroll
                    for (int nt2 = 0; nt2 < 4; nt2++) {
                        uint32_t bb[4];
                        ldsm_x4(bb, tile + SW128(b_base + nt2 * 2048u + 32 * kc));
                        mma16816(acc[nt2 * 2],     a1f, bb);
                        mma16816(acc[nt2 * 2 + 1], a1f, bb + 2);
                        mma16816(acc[nt2 * 2],     a2f, bb);
                        mma16816(acc[nt2 * 2 + 1], a2f, bb + 2);
                    }
                }
            }
        }

        // epilogue (results carry 1024x scale)
        #pragma unroll
        for (int nt = 0; nt < 8; nt++) {
            const int oc = nt * 8 + oc0;
            float* p0 = gout + (size_t)oc * HW + y * 128 + px0;
            float* p1 = p0 + HW;
            if (PASS == 0) {
                p0[0] = acc[nt][0]; p1[0] = acc[nt][1];
                p0[8] = acc[nt][2]; p1[8] = acc[nt][3];
            } else {
                const float ba = __ldg(b1 + oc), bbv = __ldg(b1 + oc + 1);
                p0[0] = fmaxf((p0[0] + acc[nt][0]) * OUT_SCALE + ba,  0.f);
                p1[0] = fmaxf((p1[0] + acc[nt][1]) * OUT_SCALE + bbv, 0.f);
                p0[8] = fmaxf((p0[8] + acc[nt][2]) * OUT_SCALE + ba,  0.f);
                p1[8] = fmaxf((p1[8] + acc[nt][3]) * OUT_SCALE + bbv, 0.f);
            }
        }
        cp_wait_all();
        __syncthreads();
    }
}

// =====================================================================
// Fused 1x1 conv (64->80) + sigmoid + 3x3 peak + argmax
// =====================================================================
__global__ __launch_bounds__(128, 4) void clspeak_kernel(
    const float* __restrict__ w2, const float* __restrict__ b2)
{
    __shared__ float s_w[80 * 64];
    __shared__ float s_b[80];
    __shared__ float s_cls[20 * 104];

    const int bx = blockIdx.x, by = blockIdx.y, b = blockIdx.z;
    const int ox = bx * 8, oy = by * 8;
    const int tid = threadIdx.x;
    const float NEG = -1e30f;

    for (int e = tid; e < 80 * 64; e += 128) s_w[e] = w2[e];
    if (tid < 80) s_b[tid] = b2[tid];

    unsigned long long fd[32];
    bool inimg = false;
    if (tid < 100) {
        int iy = tid / 10, ix = tid - iy * 10;
        int gy = oy + iy - 1, gx = ox + ix - 1;
        inimg = (gy >= 0 && gy < HH && gx >= 0 && gx < WW);
        const float* fp = g_featc + (size_t)b * 64 * HW + gy * WW + gx;
        #pragma unroll
        for (int i = 0; i < 32; i++) {
            float a = inimg ? fp[(2 * i) * HW]     : 0.f;
            float c = inimg ? fp[(2 * i + 1) * HW] : 0.f;
            fd[i] = pk2(a, c);
        }
    }
    __syncthreads();

    const int py = (tid >> 3) + 1, px = (tid & 7) + 1;
    const int pp = py * 10 + px;
    float best = -1.f;
    int cat = 0;

    for (int g = 0; g < 4; g++) {
        if (tid < 100) {
            #pragma unroll
            for (int cp = 0; cp < 10; cp++) {
                const int c0 = g * 20 + 2 * cp;
                unsigned long long a0 = 0ull, a1 = 0ull;
                const ulonglong2* w0 = (const ulonglong2*)(s_w + c0 * 64);
                const ulonglong2* w1 = (const ulonglong2*)(s_w + (c0 + 1) * 64);
                #pragma unroll
                for (int i = 0; i < 16; i++) {
                    ulonglong2 wa = w0[i];
                    ulonglong2 wb = w1[i];
                    a0 = fma2(fd[2 * i],     wa.x, a0);
                    a0 = fma2(fd[2 * i + 1], wa.y, a0);
                    a1 = fma2(fd[2 * i],     wb.x, a1);
                    a1 = fma2(fd[2 * i + 1], wb.y, a1);
                }
                float2 u0 = upk(a0), u1 = upk(a1);
                float v0 = u0.x + u0.y + s_b[c0];
                float v1 = u1.x + u1.y + s_b[c0 + 1];
                v0 = 1.f / (1.f + expf(-v0));
                v1 = 1.f / (1.f + expf(-v1));
                if (!inimg) { v0 = NEG; v1 = NEG; }
                s_cls[(2 * cp)     * 104 + tid] = v0;
                s_cls[(2 * cp + 1) * 104 + tid] = v1;
            }
        }
        __syncthreads();
        if (tid < 64) {
            #pragma unroll 4
            for (int c = 0; c < 20; c++) {
                const float* row = s_cls + c * 104;
                float v = row[pp];
                float m = v;
                m = fmaxf(m, row[pp - 11]); m = fmaxf(m, row[pp - 10]); m = fmaxf(m, row[pp - 9]);
                m = fmaxf(m, row[pp - 1]);                               m = fmaxf(m, row[pp + 1]);
                m = fmaxf(m, row[pp + 9]);  m = fmaxf(m, row[pp + 10]); m = fmaxf(m, row[pp + 11]);
                float k = (v == m) ? v : 0.f;
                if (k > best) { best = k; cat = g * 20 + c; }
            }
        }
        __syncthreads();
    }

    if (tid < 64) {
        int gp = (oy + py - 1) * WW + ox + px - 1;
        g_score[b * HW + gp] = best;
        g_cat[b * HW + gp]   = cat;
    }
}

// =====================================================================
// top-100
// =====================================================================
#define TOPK_SMEM (8192 * 4 + 1024 * 4 + HW * 8)
__global__ __launch_bounds__(1024) void topk_kernel()
{
    extern __shared__ int smi[];
    int* hist = smi;
    int* suf  = smi + 8192;
    unsigned long long* cand = (unsigned long long*)(smi + 8192 + 1024);
    __shared__ int s_tstar, s_T, s_cnt;

    const int b = blockIdx.x;
    const int tid = threadIdx.x;
    const float* s = g_score + b * HW;

    for (int i = tid; i < 8192; i += 1024) hist[i] = 0;
    if (tid == 0) s_cnt = 0;
    __syncthreads();

    for (int j = tid; j < HW; j += 1024) {
        unsigned int u = __float_as_uint(s[j]);
        atomicAdd(&hist[u >> 19], 1);
    }
    __syncthreads();

    int seg = 0;
    #pragma unroll
    for (int k = 0; k < 8; k++) seg += hist[tid * 8 + k];
    suf[tid] = seg;
    __syncthreads();
    for (int off = 1; off < 1024; off <<= 1) {
        int v = suf[tid];
        int add = (tid + off < 1024) ? suf[tid + off] : 0;
        __syncthreads();
        suf[tid] = v + add;
        __syncthreads();
    }
    if (suf[tid] >= KTOP && (tid == 1023 || suf[tid + 1] < KTOP)) s_tstar = tid;
    __syncthreads();
    if (tid == s_tstar) {
        int acc = (tid == 1023) ? 0 : suf[tid + 1];
        for (int bb = tid * 8 + 7; bb >= tid * 8; bb--) {
            acc += hist[bb];
            if (acc >= KTOP) { s_T = bb; break; }
        }
    }
    __syncthreads();
    const int T = s_T;

    for (int j = tid; j < HW; j += 1024) {
        unsigned int u = __float_as_uint(s[j]);
        if ((int)(u >> 19) >= T) {
            int pos = atomicAdd(&s_cnt, 1);
            cand[pos] = ((unsigned long long)u << 32) | (unsigned long long)(HW - j);
        }
    }
    __syncthreads();
    const int N = s_cnt;

    for (int i = tid; i < N; i += 1024) {
        unsigned long long key = cand[i];
        int rank = 0;
        for (int j = 0; j < N; j++) rank += (cand[j] > key);
        if (rank < KTOP) {
            g_tscore[b * KTOP + rank] = __uint_as_float((unsigned int)(key >> 32));
            g_tind[b * KTOP + rank]   = HW - (int)(key & 0xFFFFFFFFull);
        }
    }
}

// =====================================================================
// reg/wh at selected points (PTS=2)
// =====================================================================
#define PTS 2
__global__ __launch_bounds__(128) void point_kernel(
    const float* __restrict__ x,
    const float* __restrict__ rw1, const float* __restrict__ rb1,
    const float* __restrict__ rw2, const float* __restrict__ rb2,
    const float* __restrict__ ww1, const float* __restrict__ wb1,
    const float* __restrict__ ww2, const float* __restrict__ wb2)
{
    __shared__ float sx[PTS][576];
    __shared__ int   sp[PTS];
    __shared__ float sfa[128][PTS + 1];
    __shared__ float sres[PTS][4];

    const int g = blockIdx.x, b = blockIdx.y;
    const int tid = threadIdx.x;

    if (tid < PTS) sp[tid] = g_tind[b * KTOP + g * PTS + tid];
    __syncthreads();

    for (int e = tid; e < PTS * 576; e += 128) {
        int pt = e / 576;
        int r  = e - pt * 576;
        int c  = r / 9;
        int k9 = r - c * 9;
        int dy = k9 / 3 - 1, dx = k9 % 3 - 1;
        int p = sp[pt];
        int gy = (p >> 7) + dy, gx = (p & 127) + dx;
        float v = 0.f;
        if (gy >= 0 && gy < HH && gx >= 0 && gx < WW)
            v = x[((size_t)b * CINC + c) * HW + gy * WW + gx];
        sx[pt][r] = v;
    }
    __syncthreads();

    const float* wrow = (tid < 64) ? (rw1 + tid * 576) : (ww1 + (tid - 64) * 576);
    float bias = (tid < 64) ? rb1[tid] : wb1[tid - 64];
    float acc[PTS];
    #pragma unroll
    for (int pt = 0; pt < PTS; pt++) acc[pt] = bias;

    for (int j = 0; j < 576; j += 4) {
        float4 w4 = *(const float4*)(wrow + j);
        #pragma unroll
        for (int q = 0; q < 4; q++) {
            float w = (q == 0) ? w4.x : (q == 1) ? w4.y : (q == 2) ? w4.z : w4.w;
            #pragma unroll
            for (int pt = 0; pt < PTS; pt++)
                acc[pt] = fmaf(w, sx[pt][j + q], acc[pt]);
        }
    }
    #pragma unroll
    for (int pt = 0; pt < PTS; pt++) sfa[tid][pt] = fmaxf(acc[pt], 0.f);
    __syncthreads();

    if (tid < PTS * 4) {
        int pt = tid >> 2, o = tid & 3;
        float sv;
        if (o < 2) {
            sv = rb2[o];
            for (int i = 0; i < 64; i++) sv = fmaf(sfa[i][pt], rw2[o * 64 + i], sv);
            sv = 1.f / (1.f + expf(-sv));
        } else {
            int oo = o - 2;
            sv = wb2[oo];
            for (int i = 0; i < 64; i++) sv = fmaf(sfa[64 + i][pt], ww2[oo * 64 + i], sv);
            sv = expf(sv);
        }
        sres[pt][o] = sv;
    }
    __syncthreads();

    if (tid < PTS) {
        int p = sp[tid];
        float cx = (float)(p & 127) + sres[tid][0];
        float cy = (float)(p >> 7)  + sres[tid][1];
        float wv = sres[tid][2], hv = sres[tid][3];
        int k = b * KTOP + g * PTS + tid;
        g_boxes[k * 4 + 0] = (cx - wv * 0.5f) * 4.f;
        g_boxes[k * 4 + 1] = (cy - hv * 0.5f) * 4.f;
        g_boxes[k * 4 + 2] = (cx + wv * 0.5f) * 4.f;
        g_boxes[k * 4 + 3] = (cy + hv * 0.5f) * 4.f;
    }
}

// =====================================================================
// NMS + output
// =====================================================================
__global__ __launch_bounds__(128) void nms_kernel(float* __restrict__ out)
{
    const int b = blockIdx.x;
    const int tid = threadIdx.x;
    __shared__ float bx[KTOP][4];
    __shared__ float barea[KTOP];
    __shared__ int keep[KTOP];

    float score = 0.f; int cat = 0;
    if (tid < KTOP) {
        int k = b * KTOP + tid;
        score = g_tscore[k];
        cat   = g_cat[b * HW + g_tind[k]];
        float x1 = g_boxes[k * 4 + 0], y1 = g_boxes[k * 4 + 1];
        float x2 = g_boxes[k * 4 + 2], y2 = g_boxes[k * 4 + 3];
        bx[tid][0] = x1; bx[tid][1] = y1; bx[tid][2] = x2; bx[tid][3] = y2;
        barea[tid] = (x2 - x1) * (y2 - y1);
        keep[tid] = (score > 0.2f) ? 1 : 0;
    }
    __syncthreads();

    for (int i = 0; i < KTOP - 1; i++) {
        if (tid < KTOP && tid > i && keep[i]) {
            float xx1 = fmaxf(bx[i][0], bx[tid][0]);
            float yy1 = fmaxf(bx[i][1], bx[tid][1]);
            float xx2 = fminf(bx[i][2], bx[tid][2]);
            float yy2 = fminf(bx[i][3], bx[tid][3]);
            float iw = fmaxf(xx2 - xx1, 0.f);
            float ih = fmaxf(yy2 - yy1, 0.f);
            float inter = iw * ih;
            float iou = inter / (barea[i] + barea[tid] - inter + 1e-9f);
            if (iou > 0.5f) keep[tid] = 0;
        }
        __syncthreads();
    }

    if (tid < KTOP) {
        int base = b * KTOP + tid;
        out[base * 4 + 0] = bx[tid][0];
        out[base * 4 + 1] = bx[tid][1];
        out[base * 4 + 2] = bx[tid][2];
        out[base * 4 + 3] = bx[tid][3];
        out[6400 + base] = (float)cat;
        out[8000 + base] = score;
        out[9600 + base] = keep[tid] ? 1.f : 0.f;
    }
}

// =====================================================================
extern "C" void kernel_launch(void* const* d_in, const int* in_sizes, int n_in,
                              void* d_out, int out_size)
{
    const float* x      = (const float*)d_in[0];
    const float* cls_w1 = (const float*)d_in[1];
    const float* cls_b1 = (const float*)d_in[2];
    const float* cls_w2 = (const float*)d_in[3];
    const float* cls_b2 = (const float*)d_in[4];
    const float* reg_w1 = (const float*)d_in[5];
    const float* reg_b1 = (const float*)d_in[6];
    const float* reg_w2 = (const float*)d_in[7];
    const float* reg_b2 = (const float*)d_in[8];
    const float* wh_w1  = (const float*)d_in[9];
    const float* wh_b1  = (const float*)d_in[10];
    const float* wh_w2  = (const float*)d_in[11];
    const float* wh_b2  = (const float*)d_in[12];
    float* out = (float*)d_out;

    cudaFuncSetAttribute(conv_mma_kernel<0>, cudaFuncAttributeMaxDynamicSharedMemorySize, CONVM_SMEM);
    cudaFuncSetAttribute(conv_mma_kernel<1>, cudaFuncAttributeMaxDynamicSharedMemorySize, CONVM_SMEM);
    cudaFuncSetAttribute(topk_kernel, cudaFuncAttributeMaxDynamicSharedMemorySize, TOPK_SMEM);

    xsplit_kernel<<<dim3(128, BATCH), 256>>>(x);
    wprep_kernel<<<18, 256>>>(cls_w1);
    conv_mma_kernel<0><<<dim3(16, BATCH), 256, CONVM_SMEM>>>(cls_b1);
    conv_mma_kernel<1><<<dim3(16, BATCH), 256, CONVM_SMEM>>>(cls_b1);
    clspeak_kernel<<<dim3(16, 16, BATCH), 128>>>(cls_w2, cls_b2);
    topk_kernel<<<BATCH, 1024, TOPK_SMEM>>>();
    point_kernel<<<dim3(50, BATCH), 128>>>(x, reg_w1, reg_b1, reg_w2, reg_b2,
                                           wh_w1, wh_b1, wh_w2, wh_b2);
    nms_kernel<<<BATCH, 128>>>(out);
}

// round 14
// speedup vs baseline: 1.2764x; 1.1049x over previous
#include <cuda_runtime.h>
#include <cuda_fp16.h>
#include <math.h>
#include <stdint.h>

#define BATCH 16
#define CINC 64
#define HH 128
#define WW 128
#define HW 16384
#define NCLS 80
#define KTOP 100

// ---------------- device scratch ----------------
__device__ float g_featc[BATCH * 64 * HW];   // relu(conv3x3) cls branch
__device__ float g_score[BATCH * HW];
__device__ int   g_cat  [BATCH * HW];
__device__ float g_tscore[BATCH * KTOP];
__device__ int   g_tind  [BATCH * KTOP];
__device__ float g_boxes[BATCH * KTOP * 4];

// fp16 split input (x*16): [s in {0,1}][b*128+R][px*64+cin] (8192 elems/row)
#define XS_ELEMS_PER_SPLIT ((size_t)BATCH * 128 * 8192)
__device__ __half g_xs[2 * XS_ELEMS_PER_SPLIT];
// pre-swizzled fp16 split weights (w*64): [pass*9+tap][4096 elems, SW128]
__device__ __half g_wsw[18 * 4096];

#define SW128(o) ((o) ^ (((o) >> 3) & 0x70))
#define OUT_SCALE (1.f / 1024.f)

// ---------------- f32x2 helpers (clspeak) ----------------
__device__ __forceinline__ unsigned long long pk2(float lo, float hi) {
    unsigned long long r;
    asm("mov.b64 %0, {%1, %2};" : "=l"(r) : "r"(__float_as_uint(lo)), "r"(__float_as_uint(hi)));
    return r;
}
__device__ __forceinline__ unsigned long long fma2(unsigned long long a, unsigned long long b,
                                                   unsigned long long c) {
    unsigned long long d;
    asm("fma.rn.f32x2 %0, %1, %2, %3;" : "=l"(d) : "l"(a), "l"(b), "l"(c));
    return d;
}
__device__ __forceinline__ float2 upk(unsigned long long v) {
    unsigned int a, b;
    asm("mov.b64 {%0, %1}, %2;" : "=r"(a), "=r"(b) : "l"(v));
    return make_float2(__uint_as_float(a), __uint_as_float(b));
}

// ---------------- warp-mma / cp.async helpers ----------------
__device__ __forceinline__ uint32_t smem_u32(const void* p) {
    uint32_t a;
    asm("{ .reg .u64 t; cvta.to.shared.u64 t, %1; cvt.u32.u64 %0, t; }" : "=r"(a) : "l"(p));
    return a;
}
__device__ __forceinline__ void ldsm_x4(uint32_t* r, uint32_t addr) {
    asm volatile("ldmatrix.sync.aligned.m8n8.x4.shared.b16 {%0,%1,%2,%3}, [%4];"
        : "=r"(r[0]), "=r"(r[1]), "=r"(r[2]), "=r"(r[3]) : "r"(addr));
}
__device__ __forceinline__ void mma16816(float* d, const uint32_t* a, const uint32_t* b) {
    asm volatile(
        "mma.sync.aligned.m16n8k16.row.col.f32.f16.f16.f32 "
        "{%0,%1,%2,%3}, {%4,%5,%6,%7}, {%8,%9}, {%0,%1,%2,%3};"
        : "+f"(d[0]), "+f"(d[1]), "+f"(d[2]), "+f"(d[3])
        : "r"(a[0]), "r"(a[1]), "r"(a[2]), "r"(a[3]), "r"(b[0]), "r"(b[1]));
}
__device__ __forceinline__ void cp_async16(uint32_t dst, const void* src, bool valid) {
    int sz = valid ? 16 : 0;
    asm volatile("cp.async.cg.shared.global [%0], [%1], 16, %2;"
                 :: "r"(dst), "l"(src), "r"(sz) : "memory");
}
__device__ __forceinline__ void cp_commit() {
    asm volatile("cp.async.commit_group;" ::: "memory");
}
__device__ __forceinline__ void cp_wait_all() {
    asm volatile("cp.async.wait_group 0;" ::: "memory");
}

// =====================================================================
// Prep 1: split x*16 into 2 fp16 parts, layout [s][b*128+R][px*64+cin]
// =====================================================================
__global__ __launch_bounds__(256) void xsplit_kernel(const float* __restrict__ x)
{
    __shared__ float tile[64 * 128];
    const int R = blockIdx.x, b = blockIdx.y;
    const int tid = threadIdx.x;

    for (int e = tid; e < 8192; e += 256) {
        int cin = e >> 7, px = e & 127;
        tile[e] = x[((size_t)(b * 64 + cin) * 128 + R) * 128 + px];
    }
    __syncthreads();

    const size_t rowbase = ((size_t)b * 128 + R) * 8192;
    for (int e = tid; e < 4096; e += 256) {
        int e2 = e * 2;
        int px = e2 >> 6, cin0 = e2 & 63;
        float f0 = tile[cin0 * 128 + px] * 16.f;
        float f1 = tile[(cin0 + 1) * 128 + px] * 16.f;
        __half h10 = __float2half_rn(f0);
        __half h11 = __float2half_rn(f1);
        __half h20 = __float2half_rn(f0 - __half2float(h10));
        __half h21 = __float2half_rn(f1 - __half2float(h11));
        size_t eb = rowbase + e2;
        g_xs[eb] = h10; g_xs[eb + 1] = h11;
        g_xs[XS_ELEMS_PER_SPLIT + eb]     = h20;
        g_xs[XS_ELEMS_PER_SPLIT + eb + 1] = h21;
    }
}

// =====================================================================
// Prep 2: split + pre-swizzle weights (w*64): g_wsw[pass*9+tap]
// =====================================================================
__global__ __launch_bounds__(256) void wprep_kernel(const float* __restrict__ w1)
{
    const int t = blockIdx.x;          // 0..17 = pass*9 + tap
    const int pass = t / 9, tap = t - pass * 9;
    const int tid = threadIdx.x;
    for (int e = tid; e < 4096; e += 256) {
        int oc = e >> 6, cin = e & 63;
        float f = w1[oc * 576 + cin * 9 + tap] * 64.f;
        __half h1 = __float2half_rn(f);
        __half out = pass ? __float2half_rn(f - __half2float(h1)) : h1;
        uint32_t o = SW128((uint32_t)e * 2);
        g_wsw[(size_t)t * 4096 + (o >> 1)] = out;
    }
}

// =====================================================================
// conv via warp-level mma.sync (fp16, 4-term), 2 passes, cp.async staging.
// CTA = (rowgroup of 8, batch), 512 threads / 16 warps:
//   warp = (px-group w&7: 16 px) x (oc-half w>>3: 32 oc).
// A: 4-slot ring of 130-row tiles staged by cp.async (zfill boundaries).
// B: 9 pre-swizzled tap tiles.
// =====================================================================
#define BT_OFF 0u
#define AT_OFF 73728u
#define SLOT_STRIDE 33792u
#define SPLIT_STRIDE 16896u
#define CONVM_SMEM (73728 + 4 * 33792)
#define CONV_THREADS 512

// stage one input row (2 splits x 130 px x 128B) into ring slot via cp.async
__device__ __forceinline__ void cp_a_row(char* smem, int b, int R, int slot, int tid) {
    #pragma unroll
    for (int j = 0; j < 5; j++) {
        int c = j * CONV_THREADS + tid;
        if (c < 2080) {
            int s = (c >= 1040) ? 1 : 0;
            int r = c - s * 1040;
            int px_dst = r >> 3;
            int w16 = (r & 7) * 16;
            int px_src = px_dst - 1;
            bool valid = (R >= 0 && R < 128 && px_src >= 0 && px_src < 128);
            const char* src = (const char*)g_xs
                + (size_t)s * XS_ELEMS_PER_SPLIT * 2
                + (valid ? ((((size_t)b * 128 + R) * 8192 + (size_t)px_src * 64) * 2 + w16) : 0);
            uint32_t o = ((uint32_t)px_dst) * 128 + (uint32_t)w16;
            uint32_t dst = smem_u32(smem + AT_OFF + slot * SLOT_STRIDE
                                    + s * SPLIT_STRIDE + SW128(o));
            cp_async16(dst, src, valid);
        }
    }
}

template<int PASS>
__global__ __launch_bounds__(CONV_THREADS, 1) void conv_mma_kernel(const float* __restrict__ b1)
{
    extern __shared__ char smem[];
    const uint32_t sb = smem_u32(smem);
    const int g = blockIdx.x, b = blockIdx.y;
    const int tid = threadIdx.x;
    const int w = tid >> 5, lane = tid & 31;
    const int wpx = w & 7;          // px group (16 px)
    const int woc = w >> 3;         // oc half (32 oc)
    const int Y0 = g * 8;
    const int q = lane >> 3, rr = lane & 7;

    const uint32_t a_row = (uint32_t)(wpx * 16 + rr + 8 * (q & 1));  // tile row = px + kx
    const uint32_t a_sub = (uint32_t)(16 * (q >> 1));
    const uint32_t b_base = (uint32_t)((8 * (q >> 1) + rr) * 128 + 16 * (q & 1))
                          + (uint32_t)(woc * 2) * 2048u;
    const int px0 = wpx * 16 + (lane >> 2);
    const int oc0 = woc * 32 + 2 * (lane & 3);
    float* gout = g_featc + (size_t)b * 64 * HW;

    // stage B tiles (pre-swizzled -> pure copy): 9 x 8192 B
    for (int idx = tid; idx < 4608; idx += CONV_THREADS) {
        *(uint4*)(smem + BT_OFF + (uint32_t)idx * 16) =
            __ldg((const uint4*)((const char*)g_wsw + (size_t)PASS * 9 * 8192 + (size_t)idx * 16));
    }
    // prologue: stage rows Y0-1, Y0, Y0+1 into slots (R+1)&3
    for (int R = Y0 - 1; R <= Y0 + 1; R++) {
        cp_a_row(smem, b, R, (R + 1) & 3, tid);
    }
    cp_commit();
    cp_wait_all();
    __syncthreads();

    for (int r0 = 0; r0 < 8; r0++) {
        const int y = Y0 + r0;
        // prefetch row y+2 into the free slot (y+3)&3; overlaps with compute
        if (r0 < 7) {
            cp_a_row(smem, b, y + 2, (y + 3) & 3, tid);
            cp_commit();
        }

        float acc[4][4];
        #pragma unroll
        for (int i = 0; i < 4; i++)
            #pragma unroll
            for (int j = 0; j < 4; j++) acc[i][j] = 0.f;

        #pragma unroll
        for (int ky = 0; ky < 3; ky++) {
            const uint32_t slotb = sb + AT_OFF + (uint32_t)(((y + ky) & 3) * SLOT_STRIDE);
            #pragma unroll
            for (int kc = 0; kc < 4; kc++) {
                #pragma unroll
                for (int kx = 0; kx < 3; kx++) {
                    uint32_t o = (a_row + kx) * 128 + a_sub + 32 * kc;
                    uint32_t a1f[4], a2f[4];
                    ldsm_x4(a1f, slotb + SW128(o));
                    ldsm_x4(a2f, slotb + SPLIT_STRIDE + SW128(o));
                    const uint32_t tile = sb + BT_OFF + (uint32_t)((ky * 3 + kx) * 8192);
                    #pragma unroll
                    for (int nt2 = 0; nt2 < 2; nt2++) {
                        uint32_t bb[4];
                        ldsm_x4(bb, tile + SW128(b_base + nt2 * 2048u + 32 * kc));
                        mma16816(acc[nt2 * 2],     a1f, bb);
                        mma16816(acc[nt2 * 2 + 1], a1f, bb + 2);
                        mma16816(acc[nt2 * 2],     a2f, bb);
                        mma16816(acc[nt2 * 2 + 1], a2f, bb + 2);
                    }
                }
            }
        }

        // epilogue (results carry 1024x scale); la -> oc = oc0 + la*8
        #pragma unroll
        for (int la = 0; la < 4; la++) {
            const int oc = oc0 + la * 8;
            float* p0 = gout + (size_t)oc * HW + y * 128 + px0;
            float* p1 = p0 + HW;
            if (PASS == 0) {
                p0[0] = acc[la][0]; p1[0] = acc[la][1];
                p0[8] = acc[la][2]; p1[8] = acc[la][3];
            } else {
                const float ba = __ldg(b1 + oc), bbv = __ldg(b1 + oc + 1);
                p0[0] = fmaxf((p0[0] + acc[la][0]) * OUT_SCALE + ba,  0.f);
                p1[0] = fmaxf((p1[0] + acc[la][1]) * OUT_SCALE + bbv, 0.f);
                p0[8] = fmaxf((p0[8] + acc[la][2]) * OUT_SCALE + ba,  0.f);
                p1[8] = fmaxf((p1[8] + acc[la][3]) * OUT_SCALE + bbv, 0.f);
            }
        }
        cp_wait_all();
        __syncthreads();
    }
}

// =====================================================================
// Fused 1x1 conv (64->80) + sigmoid + 3x3 peak + argmax
// =====================================================================
__global__ __launch_bounds__(128, 4) void clspeak_kernel(
    const float* __restrict__ w2, const float* __restrict__ b2)
{
    __shared__ float s_w[80 * 64];
    __shared__ float s_b[80];
    __shared__ float s_cls[20 * 104];

    const int bx = blockIdx.x, by = blockIdx.y, b = blockIdx.z;
    const int ox = bx * 8, oy = by * 8;
    const int tid = threadIdx.x;
    const float NEG = -1e30f;

    for (int e = tid; e < 80 * 64; e += 128) s_w[e] = w2[e];
    if (tid < 80) s_b[tid] = b2[tid];

    unsigned long long fd[32];
    bool inimg = false;
    if (tid < 100) {
        int iy = tid / 10, ix = tid - iy * 10;
        int gy = oy + iy - 1, gx = ox + ix - 1;
        inimg = (gy >= 0 && gy < HH && gx >= 0 && gx < WW);
        const float* fp = g_featc + (size_t)b * 64 * HW + gy * WW + gx;
        #pragma unroll
        for (int i = 0; i < 32; i++) {
            float a = inimg ? fp[(2 * i) * HW]     : 0.f;
            float c = inimg ? fp[(2 * i + 1) * HW] : 0.f;
            fd[i] = pk2(a, c);
        }
    }
    __syncthreads();

    const int py = (tid >> 3) + 1, px = (tid & 7) + 1;
    const int pp = py * 10 + px;
    float best = -1.f;
    int cat = 0;

    for (int g = 0; g < 4; g++) {
        if (tid < 100) {
            #pragma unroll
            for (int cp = 0; cp < 10; cp++) {
                const int c0 = g * 20 + 2 * cp;
                unsigned long long a0 = 0ull, a1 = 0ull;
                const ulonglong2* w0 = (const ulonglong2*)(s_w + c0 * 64);
                const ulonglong2* w1 = (const ulonglong2*)(s_w + (c0 + 1) * 64);
                #pragma unroll
                for (int i = 0; i < 16; i++) {
                    ulonglong2 wa = w0[i];
                    ulonglong2 wb = w1[i];
                    a0 = fma2(fd[2 * i],     wa.x, a0);
                    a0 = fma2(fd[2 * i + 1], wa.y, a0);
                    a1 = fma2(fd[2 * i],     wb.x, a1);
                    a1 = fma2(fd[2 * i + 1], wb.y, a1);
                }
                float2 u0 = upk(a0), u1 = upk(a1);
                float v0 = u0.x + u0.y + s_b[c0];
                float v1 = u1.x + u1.y + s_b[c0 + 1];
                v0 = 1.f / (1.f + expf(-v0));
                v1 = 1.f / (1.f + expf(-v1));
                if (!inimg) { v0 = NEG; v1 = NEG; }
                s_cls[(2 * cp)     * 104 + tid] = v0;
                s_cls[(2 * cp + 1) * 104 + tid] = v1;
            }
        }
        __syncthreads();
        if (tid < 64) {
            #pragma unroll 4
            for (int c = 0; c < 20; c++) {
                const float* row = s_cls + c * 104;
                float v = row[pp];
                float m = v;
                m = fmaxf(m, row[pp - 11]); m = fmaxf(m, row[pp - 10]); m = fmaxf(m, row[pp - 9]);
                m = fmaxf(m, row[pp - 1]);                               m = fmaxf(m, row[pp + 1]);
                m = fmaxf(m, row[pp + 9]);  m = fmaxf(m, row[pp + 10]); m = fmaxf(m, row[pp + 11]);
                float k = (v == m) ? v : 0.f;
                if (k > best) { best = k; cat = g * 20 + c; }
            }
        }
        __syncthreads();
    }

    if (tid < 64) {
        int gp = (oy + py - 1) * WW + ox + px - 1;
        g_score[b * HW + gp] = best;
        g_cat[b * HW + gp]   = cat;
    }
}

// =====================================================================
// top-100
// =====================================================================
#define TOPK_SMEM (8192 * 4 + 1024 * 4 + HW * 8)
__global__ __launch_bounds__(1024) void topk_kernel()
{
    extern __shared__ int smi[];
    int* hist = smi;
    int* suf  = smi + 8192;
    unsigned long long* cand = (unsigned long long*)(smi + 8192 + 1024);
    __shared__ int s_tstar, s_T, s_cnt;

    const int b = blockIdx.x;
    const int tid = threadIdx.x;
    const float* s = g_score + b * HW;

    for (int i = tid; i < 8192; i += 1024) hist[i] = 0;
    if (tid == 0) s_cnt = 0;
    __syncthreads();

    for (int j = tid; j < HW; j += 1024) {
        unsigned int u = __float_as_uint(s[j]);
        atomicAdd(&hist[u >> 19], 1);
    }
    __syncthreads();

    int seg = 0;
    #pragma unroll
    for (int k = 0; k < 8; k++) seg += hist[tid * 8 + k];
    suf[tid] = seg;
    __syncthreads();
    for (int off = 1; off < 1024; off <<= 1) {
        int v = suf[tid];
        int add = (tid + off < 1024) ? suf[tid + off] : 0;
        __syncthreads();
        suf[tid] = v + add;
        __syncthreads();
    }
    if (suf[tid] >= KTOP && (tid == 1023 || suf[tid + 1] < KTOP)) s_tstar = tid;
    __syncthreads();
    if (tid == s_tstar) {
        int acc = (tid == 1023) ? 0 : suf[tid + 1];
        for (int bb = tid * 8 + 7; bb >= tid * 8; bb--) {
            acc += hist[bb];
            if (acc >= KTOP) { s_T = bb; break; }
        }
    }
    __syncthreads();
    const int T = s_T;

    for (int j = tid; j < HW; j += 1024) {
        unsigned int u = __float_as_uint(s[j]);
        if ((int)(u >> 19) >= T) {
            int pos = atomicAdd(&s_cnt, 1);
            cand[pos] = ((unsigned long long)u << 32) | (unsigned long long)(HW - j);
        }
    }
    __syncthreads();
    const int N = s_cnt;

    for (int i = tid; i < N; i += 1024) {
        unsigned long long key = cand[i];
        int rank = 0;
        for (int j = 0; j < N; j++) rank += (cand[j] > key);
        if (rank < KTOP) {
            g_tscore[b * KTOP + rank] = __uint_as_float((unsigned int)(key >> 32));
            g_tind[b * KTOP + rank]   = HW - (int)(key & 0xFFFFFFFFull);
        }
    }
}

// =====================================================================
// reg/wh at selected points (PTS=2)
// =====================================================================
#define PTS 2
__global__ __launch_bounds__(128) void point_kernel(
    const float* __restrict__ x,
    const float* __restrict__ rw1, const float* __restrict__ rb1,
    const float* __restrict__ rw2, const float* __restrict__ rb2,
    const float* __restrict__ ww1, const float* __restrict__ wb1,
    const float* __restrict__ ww2, const float* __restrict__ wb2)
{
    __shared__ float sx[PTS][576];
    __shared__ int   sp[PTS];
    __shared__ float sfa[128][PTS + 1];
    __shared__ float sres[PTS][4];

    const int g = blockIdx.x, b = blockIdx.y;
    const int tid = threadIdx.x;

    if (tid < PTS) sp[tid] = g_tind[b * KTOP + g * PTS + tid];
    __syncthreads();

    for (int e = tid; e < PTS * 576; e += 128) {
        int pt = e / 576;
        int r  = e - pt * 576;
        int c  = r / 9;
        int k9 = r - c * 9;
        int dy = k9 / 3 - 1, dx = k9 % 3 - 1;
        int p = sp[pt];
        int gy = (p >> 7) + dy, gx = (p & 127) + dx;
        float v = 0.f;
        if (gy >= 0 && gy < HH && gx >= 0 && gx < WW)
            v = x[((size_t)b * CINC + c) * HW + gy * WW + gx];
        sx[pt][r] = v;
    }
    __syncthreads();

    const float* wrow = (tid < 64) ? (rw1 + tid * 576) : (ww1 + (tid - 64) * 576);
    float bias = (tid < 64) ? rb1[tid] : wb1[tid - 64];
    float acc[PTS];
    #pragma unroll
    for (int pt = 0; pt < PTS; pt++) acc[pt] = bias;

    for (int j = 0; j < 576; j += 4) {
        float4 w4 = *(const float4*)(wrow + j);
        #pragma unroll
        for (int q = 0; q < 4; q++) {
            float w = (q == 0) ? w4.x : (q == 1) ? w4.y : (q == 2) ? w4.z : w4.w;
            #pragma unroll
            for (int pt = 0; pt < PTS; pt++)
                acc[pt] = fmaf(w, sx[pt][j + q], acc[pt]);
        }
    }
    #pragma unroll
    for (int pt = 0; pt < PTS; pt++) sfa[tid][pt] = fmaxf(acc[pt], 0.f);
    __syncthreads();

    if (tid < PTS * 4) {
        int pt = tid >> 2, o = tid & 3;
        float sv;
        if (o < 2) {
            sv = rb2[o];
            for (int i = 0; i < 64; i++) sv = fmaf(sfa[i][pt], rw2[o * 64 + i], sv);
            sv = 1.f / (1.f + expf(-sv));
        } else {
            int oo = o - 2;
            sv = wb2[oo];
            for (int i = 0; i < 64; i++) sv = fmaf(sfa[64 + i][pt], ww2[oo * 64 + i], sv);
            sv = expf(sv);
        }
        sres[pt][o] = sv;
    }
    __syncthreads();

    if (tid < PTS) {
        int p = sp[tid];
        float cx = (float)(p & 127) + sres[tid][0];
        float cy = (float)(p >> 7)  + sres[tid][1];
        float wv = sres[tid][2], hv = sres[tid][3];
        int k = b * KTOP + g * PTS + tid;
        g_boxes[k * 4 + 0] = (cx - wv * 0.5f) * 4.f;
        g_boxes[k * 4 + 1] = (cy - hv * 0.5f) * 4.f;
        g_boxes[k * 4 + 2] = (cx + wv * 0.5f) * 4.f;
        g_boxes[k * 4 + 3] = (cy + hv * 0.5f) * 4.f;
    }
}

// =====================================================================
// NMS + output
// =====================================================================
__global__ __launch_bounds__(128) void nms_kernel(float* __restrict__ out)
{
    const int b = blockIdx.x;
    const int tid = threadIdx.x;
    __shared__ float bx[KTOP][4];
    __shared__ float barea[KTOP];
    __shared__ int keep[KTOP];

    float score = 0.f; int cat = 0;
    if (tid < KTOP) {
        int k = b * KTOP + tid;
        score = g_tscore[k];
        cat   = g_cat[b * HW + g_tind[k]];
        float x1 = g_boxes[k * 4 + 0], y1 = g_boxes[k * 4 + 1];
        float x2 = g_boxes[k * 4 + 2], y2 = g_boxes[k * 4 + 3];
        bx[tid][0] = x1; bx[tid][1] = y1; bx[tid][2] = x2; bx[tid][3] = y2;
        barea[tid] = (x2 - x1) * (y2 - y1);
        keep[tid] = (score > 0.2f) ? 1 : 0;
    }
    __syncthreads();

    for (int i = 0; i < KTOP - 1; i++) {
        if (tid < KTOP && tid > i && keep[i]) {
            float xx1 = fmaxf(bx[i][0], bx[tid][0]);
            float yy1 = fmaxf(bx[i][1], bx[tid][1]);
            float xx2 = fminf(bx[i][2], bx[tid][2]);
            float yy2 = fminf(bx[i][3], bx[tid][3]);
            float iw = fmaxf(xx2 - xx1, 0.f);
            float ih = fmaxf(yy2 - yy1, 0.f);
            float inter = iw * ih;
            float iou = inter / (barea[i] + barea[tid] - inter + 1e-9f);
            if (iou > 0.5f) keep[tid] = 0;
        }
        __syncthreads();
    }

    if (tid < KTOP) {
        int base = b * KTOP + tid;
        out[base * 4 + 0] = bx[tid][0];
        out[base * 4 + 1] = bx[tid][1];
        out[base * 4 + 2] = bx[tid][2];
        out[base * 4 + 3] = bx[tid][3];
        out[6400 + base] = (float)cat;
        out[8000 + base] = score;
        out[9600 + base] = keep[tid] ? 1.f : 0.f;
    }
}

// =====================================================================
extern "C" void kernel_launch(void* const* d_in, const int* in_sizes, int n_in,
                              void* d_out, int out_size)
{
    const float* x      = (const float*)d_in[0];
    const float* cls_w1 = (const float*)d_in[1];
    const float* cls_b1 = (const float*)d_in[2];
    const float* cls_w2 = (const float*)d_in[3];
    const float* cls_b2 = (const float*)d_in[4];
    const float* reg_w1 = (const float*)d_in[5];
    const float* reg_b1 = (const float*)d_in[6];
    const float* reg_w2 = (const float*)d_in[7];
    const float* reg_b2 = (const float*)d_in[8];
    const float* wh_w1  = (const float*)d_in[9];
    const float* wh_b1  = (const float*)d_in[10];
    const float* wh_w2  = (const float*)d_in[11];
    const float* wh_b2  = (const float*)d_in[12];
    float* out = (float*)d_out;

    cudaFuncSetAttribute(conv_mma_kernel<0>, cudaFuncAttributeMaxDynamicSharedMemorySize, CONVM_SMEM);
    cudaFuncSetAttribute(conv_mma_kernel<1>, cudaFuncAttributeMaxDynamicSharedMemorySize, CONVM_SMEM);
    cudaFuncSetAttribute(topk_kernel, cudaFuncAttributeMaxDynamicSharedMemorySize, TOPK_SMEM);

    xsplit_kernel<<<dim3(128, BATCH), 256>>>(x);
    wprep_kernel<<<18, 256>>>(cls_w1);
    conv_mma_kernel<0><<<dim3(16, BATCH), CONV_THREADS, CONVM_SMEM>>>(cls_b1);
    conv_mma_kernel<1><<<dim3(16, BATCH), CONV_THREADS, CONVM_SMEM>>>(cls_b1);
    clspeak_kernel<<<dim3(16, 16, BATCH), 128>>>(cls_w2, cls_b2);
    topk_kernel<<<BATCH, 1024, TOPK_SMEM>>>();
    point_kernel<<<dim3(50, BATCH), 128>>>(x, reg_w1, reg_b1, reg_w2, reg_b2,
                                           wh_w1, wh_b1, wh_w2, wh_b2);
    nms_kernel<<<BATCH, 128>>>(out);
}

// round 15
// speedup vs baseline: 1.3078x; 1.0246x over previous
#include <cuda_runtime.h>
#include <cuda_fp16.h>
#include <math.h>
#include <stdint.h>

#define BATCH 16
#define CINC 64
#define HH 128
#define WW 128
#define HW 16384
#define NCLS 80
#define KTOP 100

// ---------------- device scratch ----------------
__device__ float g_featc[BATCH * 64 * HW];       // relu(conv3x3) cls branch
__device__ unsigned int g_scoreu[BATCH * HW];    // monotone-uint masked logit
__device__ int   g_cat  [BATCH * HW];
__device__ float g_tscore[BATCH * KTOP];         // logit of selected
__device__ int   g_tind  [BATCH * KTOP];
__device__ float g_boxes[BATCH * KTOP * 4];

// fp16 split input (x*16): [s in {0,1}][b*128+R][px*64+cin] (8192 elems/row)
#define XS_ELEMS_PER_SPLIT ((size_t)BATCH * 128 * 8192)
__device__ __half g_xs[2 * XS_ELEMS_PER_SPLIT];
// pre-swizzled fp16 split weights (w*64): [pass*9+tap][4096 elems, SW128]
__device__ __half g_wsw[18 * 4096];

#define SW128(o) ((o) ^ (((o) >> 3) & 0x70))
#define OUT_SCALE (1.f / 1024.f)

// ---------------- f32x2 helpers (clspeak) ----------------
__device__ __forceinline__ unsigned long long pk2(float lo, float hi) {
    unsigned long long r;
    asm("mov.b64 %0, {%1, %2};" : "=l"(r) : "r"(__float_as_uint(lo)), "r"(__float_as_uint(hi)));
    return r;
}
__device__ __forceinline__ unsigned long long fma2(unsigned long long a, unsigned long long b,
                                                   unsigned long long c) {
    unsigned long long d;
    asm("fma.rn.f32x2 %0, %1, %2, %3;" : "=l"(d) : "l"(a), "l"(b), "l"(c));
    return d;
}
__device__ __forceinline__ float2 upk(unsigned long long v) {
    unsigned int a, b;
    asm("mov.b64 {%0, %1}, %2;" : "=r"(a), "=r"(b) : "l"(v));
    return make_float2(__uint_as_float(a), __uint_as_float(b));
}

// ---------------- warp-mma / cp.async helpers ----------------
__device__ __forceinline__ uint32_t smem_u32(const void* p) {
    uint32_t a;
    asm("{ .reg .u64 t; cvta.to.shared.u64 t, %1; cvt.u32.u64 %0, t; }" : "=r"(a) : "l"(p));
    return a;
}
__device__ __forceinline__ void ldsm_x4(uint32_t* r, uint32_t addr) {
    asm volatile("ldmatrix.sync.aligned.m8n8.x4.shared.b16 {%0,%1,%2,%3}, [%4];"
        : "=r"(r[0]), "=r"(r[1]), "=r"(r[2]), "=r"(r[3]) : "r"(addr));
}
__device__ __forceinline__ void mma16816(float* d, const uint32_t* a, const uint32_t* b) {
    asm volatile(
        "mma.sync.aligned.m16n8k16.row.col.f32.f16.f16.f32 "
        "{%0,%1,%2,%3}, {%4,%5,%6,%7}, {%8,%9}, {%0,%1,%2,%3};"
        : "+f"(d[0]), "+f"(d[1]), "+f"(d[2]), "+f"(d[3])
        : "r"(a[0]), "r"(a[1]), "r"(a[2]), "r"(a[3]), "r"(b[0]), "r"(b[1]));
}
__device__ __forceinline__ void cp_async16(uint32_t dst, const void* src, bool valid) {
    int sz = valid ? 16 : 0;
    asm volatile("cp.async.cg.shared.global [%0], [%1], 16, %2;"
                 :: "r"(dst), "l"(src), "r"(sz) : "memory");
}
__device__ __forceinline__ void cp_commit() {
    asm volatile("cp.async.commit_group;" ::: "memory");
}
__device__ __forceinline__ void cp_wait_all() {
    asm volatile("cp.async.wait_group 0;" ::: "memory");
}

// =====================================================================
// Prep 1: split x*16 into 2 fp16 parts, layout [s][b*128+R][px*64+cin]
// =====================================================================
__global__ __launch_bounds__(256) void xsplit_kernel(const float* __restrict__ x)
{
    __shared__ float tile[64 * 128];
    const int R = blockIdx.x, b = blockIdx.y;
    const int tid = threadIdx.x;

    for (int e = tid; e < 8192; e += 256) {
        int cin = e >> 7, px = e & 127;
        tile[e] = x[((size_t)(b * 64 + cin) * 128 + R) * 128 + px];
    }
    __syncthreads();

    const size_t rowbase = ((size_t)b * 128 + R) * 8192;
    for (int e = tid; e < 4096; e += 256) {
        int e2 = e * 2;
        int px = e2 >> 6, cin0 = e2 & 63;
        float f0 = tile[cin0 * 128 + px] * 16.f;
        float f1 = tile[(cin0 + 1) * 128 + px] * 16.f;
        __half h10 = __float2half_rn(f0);
        __half h11 = __float2half_rn(f1);
        __half h20 = __float2half_rn(f0 - __half2float(h10));
        __half h21 = __float2half_rn(f1 - __half2float(h11));
        size_t eb = rowbase + e2;
        g_xs[eb] = h10; g_xs[eb + 1] = h11;
        g_xs[XS_ELEMS_PER_SPLIT + eb]     = h20;
        g_xs[XS_ELEMS_PER_SPLIT + eb + 1] = h21;
    }
}

// =====================================================================
// Prep 2: split + pre-swizzle weights (w*64): g_wsw[pass*9+tap]
// =====================================================================
__global__ __launch_bounds__(256) void wprep_kernel(const float* __restrict__ w1)
{
    const int t = blockIdx.x;          // 0..17 = pass*9 + tap
    const int pass = t / 9, tap = t - pass * 9;
    const int tid = threadIdx.x;
    for (int e = tid; e < 4096; e += 256) {
        int oc = e >> 6, cin = e & 63;
        float f = w1[oc * 576 + cin * 9 + tap] * 64.f;
        __half h1 = __float2half_rn(f);
        __half out = pass ? __float2half_rn(f - __half2float(h1)) : h1;
        uint32_t o = SW128((uint32_t)e * 2);
        g_wsw[(size_t)t * 4096 + (o >> 1)] = out;
    }
}

// =====================================================================
// conv via warp-level mma.sync (fp16, 4-term), 2 passes, cp.async staging.
// CTA = (rowgroup of 8, batch), 512 threads / 16 warps.
// =====================================================================
#define BT_OFF 0u
#define AT_OFF 73728u
#define SLOT_STRIDE 33792u
#define SPLIT_STRIDE 16896u
#define CONVM_SMEM (73728 + 4 * 33792)
#define CONV_THREADS 512

__device__ __forceinline__ void cp_a_row(char* smem, int b, int R, int slot, int tid) {
    #pragma unroll
    for (int j = 0; j < 5; j++) {
        int c = j * CONV_THREADS + tid;
        if (c < 2080) {
            int s = (c >= 1040) ? 1 : 0;
            int r = c - s * 1040;
            int px_dst = r >> 3;
            int w16 = (r & 7) * 16;
            int px_src = px_dst - 1;
            bool valid = (R >= 0 && R < 128 && px_src >= 0 && px_src < 128);
            const char* src = (const char*)g_xs
                + (size_t)s * XS_ELEMS_PER_SPLIT * 2
                + (valid ? ((((size_t)b * 128 + R) * 8192 + (size_t)px_src * 64) * 2 + w16) : 0);
            uint32_t o = ((uint32_t)px_dst) * 128 + (uint32_t)w16;
            uint32_t dst = smem_u32(smem + AT_OFF + slot * SLOT_STRIDE
                                    + s * SPLIT_STRIDE + SW128(o));
            cp_async16(dst, src, valid);
        }
    }
}

template<int PASS>
__global__ __launch_bounds__(CONV_THREADS, 1) void conv_mma_kernel(const float* __restrict__ b1)
{
    extern __shared__ char smem[];
    const uint32_t sb = smem_u32(smem);
    const int g = blockIdx.x, b = blockIdx.y;
    const int tid = threadIdx.x;
    const int w = tid >> 5, lane = tid & 31;
    const int wpx = w & 7;
    const int woc = w >> 3;
    const int Y0 = g * 8;
    const int q = lane >> 3, rr = lane & 7;

    const uint32_t a_row = (uint32_t)(wpx * 16 + rr + 8 * (q & 1));
    const uint32_t a_sub = (uint32_t)(16 * (q >> 1));
    const uint32_t b_base = (uint32_t)((8 * (q >> 1) + rr) * 128 + 16 * (q & 1))
                          + (uint32_t)(woc * 2) * 2048u;
    const int px0 = wpx * 16 + (lane >> 2);
    const int oc0 = woc * 32 + 2 * (lane & 3);
    float* gout = g_featc + (size_t)b * 64 * HW;

    for (int idx = tid; idx < 4608; idx += CONV_THREADS) {
        *(uint4*)(smem + BT_OFF + (uint32_t)idx * 16) =
            __ldg((const uint4*)((const char*)g_wsw + (size_t)PASS * 9 * 8192 + (size_t)idx * 16));
    }
    for (int R = Y0 - 1; R <= Y0 + 1; R++) {
        cp_a_row(smem, b, R, (R + 1) & 3, tid);
    }
    cp_commit();
    cp_wait_all();
    __syncthreads();

    for (int r0 = 0; r0 < 8; r0++) {
        const int y = Y0 + r0;
        if (r0 < 7) {
            cp_a_row(smem, b, y + 2, (y + 3) & 3, tid);
            cp_commit();
        }

        float acc[4][4];
        #pragma unroll
        for (int i = 0; i < 4; i++)
            #pragma unroll
            for (int j = 0; j < 4; j++) acc[i][j] = 0.f;

        #pragma unroll
        for (int ky = 0; ky < 3; ky++) {
            const uint32_t slotb = sb + AT_OFF + (uint32_t)(((y + ky) & 3) * SLOT_STRIDE);
            #pragma unroll
            for (int kc = 0; kc < 4; kc++) {
                #pragma unroll
                for (int kx = 0; kx < 3; kx++) {
                    uint32_t o = (a_row + kx) * 128 + a_sub + 32 * kc;
                    uint32_t a1f[4], a2f[4];
                    ldsm_x4(a1f, slotb + SW128(o));
                    ldsm_x4(a2f, slotb + SPLIT_STRIDE + SW128(o));
                    const uint32_t tile = sb + BT_OFF + (uint32_t)((ky * 3 + kx) * 8192);
                    #pragma unroll
                    for (int nt2 = 0; nt2 < 2; nt2++) {
                        uint32_t bb[4];
                        ldsm_x4(bb, tile + SW128(b_base + nt2 * 2048u + 32 * kc));
                        mma16816(acc[nt2 * 2],     a1f, bb);
                        mma16816(acc[nt2 * 2 + 1], a1f, bb + 2);
                        mma16816(acc[nt2 * 2],     a2f, bb);
                        mma16816(acc[nt2 * 2 + 1], a2f, bb + 2);
                    }
                }
            }
        }

        #pragma unroll
        for (int la = 0; la < 4; la++) {
            const int oc = oc0 + la * 8;
            float* p0 = gout + (size_t)oc * HW + y * 128 + px0;
            float* p1 = p0 + HW;
            if (PASS == 0) {
                p0[0] = acc[la][0]; p1[0] = acc[la][1];
                p0[8] = acc[la][2]; p1[8] = acc[la][3];
            } else {
                const float ba = __ldg(b1 + oc), bbv = __ldg(b1 + oc + 1);
                p0[0] = fmaxf((p0[0] + acc[la][0]) * OUT_SCALE + ba,  0.f);
                p1[0] = fmaxf((p1[0] + acc[la][1]) * OUT_SCALE + bbv, 0.f);
                p0[8] = fmaxf((p0[8] + acc[la][2]) * OUT_SCALE + ba,  0.f);
                p1[8] = fmaxf((p1[8] + acc[la][3]) * OUT_SCALE + bbv, 0.f);
            }
        }
        cp_wait_all();
        __syncthreads();
    }
}

// =====================================================================
// Fused 1x1 conv (64->80) + LOGIT-SPACE 3x3 peak + argmax.
// No sigmoid here (monotonic; applied to the 1600 winners in nms).
// Stores monotone-uint keys (handles negative logits).
// =====================================================================
__global__ __launch_bounds__(128, 4) void clspeak_kernel(
    const float* __restrict__ w2, const float* __restrict__ b2)
{
    __shared__ float s_w[80 * 64];
    __shared__ float s_b[80];
    __shared__ float s_cls[20 * 104];

    const int bx = blockIdx.x, by = blockIdx.y, b = blockIdx.z;
    const int ox = bx * 8, oy = by * 8;
    const int tid = threadIdx.x;
    const float NEG = -1e30f;

    for (int e = tid; e < 80 * 64; e += 128) s_w[e] = w2[e];
    if (tid < 80) s_b[tid] = b2[tid];

    unsigned long long fd[32];
    bool inimg = false;
    if (tid < 100) {
        int iy = tid / 10, ix = tid - iy * 10;
        int gy = oy + iy - 1, gx = ox + ix - 1;
        inimg = (gy >= 0 && gy < HH && gx >= 0 && gx < WW);
        const float* fp = g_featc + (size_t)b * 64 * HW + gy * WW + gx;
        #pragma unroll
        for (int i = 0; i < 32; i++) {
            float a = inimg ? fp[(2 * i) * HW]     : 0.f;
            float c = inimg ? fp[(2 * i + 1) * HW] : 0.f;
            fd[i] = pk2(a, c);
        }
    }
    __syncthreads();

    const int py = (tid >> 3) + 1, px = (tid & 7) + 1;
    const int pp = py * 10 + px;
    float best = NEG;
    int cat = 0;

    for (int g = 0; g < 4; g++) {
        if (tid < 100) {
            #pragma unroll
            for (int cp = 0; cp < 10; cp++) {
                const int c0 = g * 20 + 2 * cp;
                unsigned long long a0 = 0ull, a1 = 0ull;
                const ulonglong2* w0 = (const ulonglong2*)(s_w + c0 * 64);
                const ulonglong2* w1 = (const ulonglong2*)(s_w + (c0 + 1) * 64);
                #pragma unroll
                for (int i = 0; i < 16; i++) {
                    ulonglong2 wa = w0[i];
                    ulonglong2 wb = w1[i];
                    a0 = fma2(fd[2 * i],     wa.x, a0);
                    a0 = fma2(fd[2 * i + 1], wa.y, a0);
                    a1 = fma2(fd[2 * i],     wb.x, a1);
                    a1 = fma2(fd[2 * i + 1], wb.y, a1);
                }
                float2 u0 = upk(a0), u1 = upk(a1);
                float v0 = u0.x + u0.y + s_b[c0];
                float v1 = u1.x + u1.y + s_b[c0 + 1];
                if (!inimg) { v0 = NEG; v1 = NEG; }
                s_cls[(2 * cp)     * 104 + tid] = v0;
                s_cls[(2 * cp + 1) * 104 + tid] = v1;
            }
        }
        __syncthreads();
        if (tid < 64) {
            #pragma unroll 4
            for (int c = 0; c < 20; c++) {
                const float* row = s_cls + c * 104;
                float v = row[pp];
                float m = v;
                m = fmaxf(m, row[pp - 11]); m = fmaxf(m, row[pp - 10]); m = fmaxf(m, row[pp - 9]);
                m = fmaxf(m, row[pp - 1]);                               m = fmaxf(m, row[pp + 1]);
                m = fmaxf(m, row[pp + 9]);  m = fmaxf(m, row[pp + 10]); m = fmaxf(m, row[pp + 11]);
                float k = (v == m) ? v : NEG;
                if (k > best) { best = k; cat = g * 20 + c; }
            }
        }
        __syncthreads();
    }

    if (tid < 64) {
        int gp = (oy + py - 1) * WW + ox + px - 1;
        unsigned int u = __float_as_uint(best);
        unsigned int mu = (u & 0x80000000u) ? ~u : (u | 0x80000000u);
        g_scoreu[b * HW + gp] = mu;
        g_cat[b * HW + gp]    = cat;
    }
}

// =====================================================================
// top-100 on monotone-uint keys; writes back logits.
// =====================================================================
#define TOPK_SMEM (8192 * 4 + 1024 * 4 + HW * 8)
__global__ __launch_bounds__(1024) void topk_kernel()
{
    extern __shared__ int smi[];
    int* hist = smi;
    int* suf  = smi + 8192;
    unsigned long long* cand = (unsigned long long*)(smi + 8192 + 1024);
    __shared__ int s_tstar, s_T, s_cnt;

    const int b = blockIdx.x;
    const int tid = threadIdx.x;
    const unsigned int* s = g_scoreu + b * HW;

    for (int i = tid; i < 8192; i += 1024) hist[i] = 0;
    if (tid == 0) s_cnt = 0;
    __syncthreads();

    for (int j = tid; j < HW; j += 1024) {
        unsigned int mu = s[j];
        atomicAdd(&hist[mu >> 19], 1);
    }
    __syncthreads();

    int seg = 0;
    #pragma unroll
    for (int k = 0; k < 8; k++) seg += hist[tid * 8 + k];
    suf[tid] = seg;
    __syncthreads();
    for (int off = 1; off < 1024; off <<= 1) {
        int v = suf[tid];
        int add = (tid + off < 1024) ? suf[tid + off] : 0;
        __syncthreads();
        suf[tid] = v + add;
        __syncthreads();
    }
    if (suf[tid] >= KTOP && (tid == 1023 || suf[tid + 1] < KTOP)) s_tstar = tid;
    __syncthreads();
    if (tid == s_tstar) {
        int acc = (tid == 1023) ? 0 : suf[tid + 1];
        for (int bb = tid * 8 + 7; bb >= tid * 8; bb--) {
            acc += hist[bb];
            if (acc >= KTOP) { s_T = bb; break; }
        }
    }
    __syncthreads();
    const int T = s_T;

    for (int j = tid; j < HW; j += 1024) {
        unsigned int mu = s[j];
        if ((int)(mu >> 19) >= T) {
            int pos = atomicAdd(&s_cnt, 1);
            cand[pos] = ((unsigned long long)mu << 32) | (unsigned long long)(HW - j);
        }
    }
    __syncthreads();
    const int N = s_cnt;

    for (int i = tid; i < N; i += 1024) {
        unsigned long long key = cand[i];
        int rank = 0;
        for (int j = 0; j < N; j++) rank += (cand[j] > key);
        if (rank < KTOP) {
            unsigned int mu = (unsigned int)(key >> 32);
            unsigned int u = (mu & 0x80000000u) ? (mu ^ 0x80000000u) : ~mu;
            g_tscore[b * KTOP + rank] = __uint_as_float(u);   // logit
            g_tind[b * KTOP + rank]   = HW - (int)(key & 0xFFFFFFFFull);
        }
    }
}

// =====================================================================
// reg/wh at selected points (PTS=2)
// =====================================================================
#define PTS 2
__global__ __launch_bounds__(128) void point_kernel(
    const float* __restrict__ x,
    const float* __restrict__ rw1, const float* __restrict__ rb1,
    const float* __restrict__ rw2, const float* __restrict__ rb2,
    const float* __restrict__ ww1, const float* __restrict__ wb1,
    const float* __restrict__ ww2, const float* __restrict__ wb2)
{
    __shared__ float sx[PTS][576];
    __shared__ int   sp[PTS];
    __shared__ float sfa[128][PTS + 1];
    __shared__ float sres[PTS][4];

    const int g = blockIdx.x, b = blockIdx.y;
    const int tid = threadIdx.x;

    if (tid < PTS) sp[tid] = g_tind[b * KTOP + g * PTS + tid];
    __syncthreads();

    for (int e = tid; e < PTS * 576; e += 128) {
        int pt = e / 576;
        int r  = e - pt * 576;
        int c  = r / 9;
        int k9 = r - c * 9;
        int dy = k9 / 3 - 1, dx = k9 % 3 - 1;
        int p = sp[pt];
        int gy = (p >> 7) + dy, gx = (p & 127) + dx;
        float v = 0.f;
        if (gy >= 0 && gy < HH && gx >= 0 && gx < WW)
            v = x[((size_t)b * CINC + c) * HW + gy * WW + gx];
        sx[pt][r] = v;
    }
    __syncthreads();

    const float* wrow = (tid < 64) ? (rw1 + tid * 576) : (ww1 + (tid - 64) * 576);
    float bias = (tid < 64) ? rb1[tid] : wb1[tid - 64];
    float acc[PTS];
    #pragma unroll
    for (int pt = 0; pt < PTS; pt++) acc[pt] = bias;

    for (int j = 0; j < 576; j += 4) {
        float4 w4 = *(const float4*)(wrow + j);
        #pragma unroll
        for (int q = 0; q < 4; q++) {
            float w = (q == 0) ? w4.x : (q == 1) ? w4.y : (q == 2) ? w4.z : w4.w;
            #pragma unroll
            for (int pt = 0; pt < PTS; pt++)
                acc[pt] = fmaf(w, sx[pt][j + q], acc[pt]);
        }
    }
    #pragma unroll
    for (int pt = 0; pt < PTS; pt++) sfa[tid][pt] = fmaxf(acc[pt], 0.f);
    __syncthreads();

    if (tid < PTS * 4) {
        int pt = tid >> 2, o = tid & 3;
        float sv;
        if (o < 2) {
            sv = rb2[o];
            for (int i = 0; i < 64; i++) sv = fmaf(sfa[i][pt], rw2[o * 64 + i], sv);
            sv = 1.f / (1.f + expf(-sv));
        } else {
            int oo = o - 2;
            sv = wb2[oo];
            for (int i = 0; i < 64; i++) sv = fmaf(sfa[64 + i][pt], ww2[oo * 64 + i], sv);
            sv = expf(sv);
        }
        sres[pt][o] = sv;
    }
    __syncthreads();

    if (tid < PTS) {
        int p = sp[tid];
        float cx = (float)(p & 127) + sres[tid][0];
        float cy = (float)(p >> 7)  + sres[tid][1];
        float wv = sres[tid][2], hv = sres[tid][3];
        int k = b * KTOP + g * PTS + tid;
        g_boxes[k * 4 + 0] = (cx - wv * 0.5f) * 4.f;
        g_boxes[k * 4 + 1] = (cy - hv * 0.5f) * 4.f;
        g_boxes[k * 4 + 2] = (cx + wv * 0.5f) * 4.f;
        g_boxes[k * 4 + 3] = (cy + hv * 0.5f) * 4.f;
    }
}

// =====================================================================
// NMS + output (sigmoid applied here to the 100 selected logits)
// =====================================================================
__global__ __launch_bounds__(128) void nms_kernel(float* __restrict__ out)
{
    const int b = blockIdx.x;
    const int tid = threadIdx.x;
    __shared__ float bx[KTOP][4];
    __shared__ float barea[KTOP];
    __shared__ int keep[KTOP];

    float score = 0.f; int cat = 0;
    if (tid < KTOP) {
        int k = b * KTOP + tid;
        float logit = g_tscore[k];
        score = 1.f / (1.f + expf(-logit));     // -1e30 -> 0 exactly
        cat   = g_cat[b * HW + g_tind[k]];
        float x1 = g_boxes[k * 4 + 0], y1 = g_boxes[k * 4 + 1];
        float x2 = g_boxes[k * 4 + 2], y2 = g_boxes[k * 4 + 3];
        bx[tid][0] = x1; bx[tid][1] = y1; bx[tid][2] = x2; bx[tid][3] = y2;
        barea[tid] = (x2 - x1) * (y2 - y1);
        keep[tid] = (score > 0.2f) ? 1 : 0;
    }
    __syncthreads();

    for (int i = 0; i < KTOP - 1; i++) {
        if (tid < KTOP && tid > i && keep[i]) {
            float xx1 = fmaxf(bx[i][0], bx[tid][0]);
            float yy1 = fmaxf(bx[i][1], bx[tid][1]);
            float xx2 = fminf(bx[i][2], bx[tid][2]);
            float yy2 = fminf(bx[i][3], bx[tid][3]);
            float iw = fmaxf(xx2 - xx1, 0.f);
            float ih = fmaxf(yy2 - yy1, 0.f);
            float inter = iw * ih;
            float iou = inter / (barea[i] + barea[tid] - inter + 1e-9f);
            if (iou > 0.5f) keep[tid] = 0;
        }
        __syncthreads();
    }

    if (tid < KTOP) {
        int base = b * KTOP + tid;
        out[base * 4 + 0] = bx[tid][0];
        out[base * 4 + 1] = bx[tid][1];
        out[base * 4 + 2] = bx[tid][2];
        out[base * 4 + 3] = bx[tid][3];
        out[6400 + base] = (float)cat;
        out[8000 + base] = score;
        out[9600 + base] = keep[tid] ? 1.f : 0.f;
    }
}

// =====================================================================
extern "C" void kernel_launch(void* const* d_in, const int* in_sizes, int n_in,
                              void* d_out, int out_size)
{
    const float* x      = (const float*)d_in[0];
    const float* cls_w1 = (const float*)d_in[1];
    const float* cls_b1 = (const float*)d_in[2];
    const float* cls_w2 = (const float*)d_in[3];
    const float* cls_b2 = (const float*)d_in[4];
    const float* reg_w1 = (const float*)d_in[5];
    const float* reg_b1 = (const float*)d_in[6];
    const float* reg_w2 = (const float*)d_in[7];
    const float* reg_b2 = (const float*)d_in[8];
    const float* wh_w1  = (const float*)d_in[9];
    const float* wh_b1  = (const float*)d_in[10];
    const float* wh_w2  = (const float*)d_in[11];
    const float* wh_b2  = (const float*)d_in[12];
    float* out = (float*)d_out;

    cudaFuncSetAttribute(conv_mma_kernel<0>, cudaFuncAttributeMaxDynamicSharedMemorySize, CONVM_SMEM);
    cudaFuncSetAttribute(conv_mma_kernel<1>, cudaFuncAttributeMaxDynamicSharedMemorySize, CONVM_SMEM);
    cudaFuncSetAttribute(topk_kernel, cudaFuncAttributeMaxDynamicSharedMemorySize, TOPK_SMEM);

    xsplit_kernel<<<dim3(128, BATCH), 256>>>(x);
    wprep_kernel<<<18, 256>>>(cls_w1);
    conv_mma_kernel<0><<<dim3(16, BATCH), CONV_THREADS, CONVM_SMEM>>>(cls_b1);
    conv_mma_kernel<1><<<dim3(16, BATCH), CONV_THREADS, CONVM_SMEM>>>(cls_b1);
    clspeak_kernel<<<dim3(16, 16, BATCH), 128>>>(cls_w2, cls_b2);
    topk_kernel<<<BATCH, 1024, TOPK_SMEM>>>();
    point_kernel<<<dim3(50, BATCH), 128>>>(x, reg_w1, reg_b1, reg_w2, reg_b2,
                                           wh_w1, wh_b1, wh_w2, wh_b2);
    nms_kernel<<<BATCH, 128>>>(out);
}

// round 16
// speedup vs baseline: 1.4177x; 1.0840x over previous
#include <cuda_runtime.h>
#include <cuda_fp16.h>
#include <math.h>
#include <stdint.h>

#define BATCH 16
#define CINC 64
#define HH 128
#define WW 128
#define HW 16384
#define NCLS 80
#define KTOP 100

// ---------------- device scratch ----------------
__device__ float g_featc[BATCH * 64 * HW];       // relu(conv3x3) cls branch
__device__ unsigned int g_scoreu[BATCH * HW];    // monotone-uint masked logit
__device__ int   g_cat  [BATCH * HW];
__device__ float g_tscore[BATCH * KTOP];         // logit of selected
__device__ int   g_tind  [BATCH * KTOP];
__device__ float g_boxes[BATCH * KTOP * 4];

// fp16 split input (x*16): [s in {0,1}][b*128+R][px*64+cin] (8192 elems/row)
#define XS_ELEMS_PER_SPLIT ((size_t)BATCH * 128 * 8192)
__device__ __half g_xs[2 * XS_ELEMS_PER_SPLIT];
// pre-swizzled fp16 split weights (w*64): [pass*9+tap][4096 elems, SW128]
__device__ __half g_wsw[18 * 4096];

#define SW128(o) ((o) ^ (((o) >> 3) & 0x70))
#define OUT_SCALE (1.f / 1024.f)

// ---------------- f32x2 helpers (clspeak) ----------------
__device__ __forceinline__ unsigned long long pk2(float lo, float hi) {
    unsigned long long r;
    asm("mov.b64 %0, {%1, %2};" : "=l"(r) : "r"(__float_as_uint(lo)), "r"(__float_as_uint(hi)));
    return r;
}
__device__ __forceinline__ unsigned long long fma2(unsigned long long a, unsigned long long b,
                                                   unsigned long long c) {
    unsigned long long d;
    asm("fma.rn.f32x2 %0, %1, %2, %3;" : "=l"(d) : "l"(a), "l"(b), "l"(c));
    return d;
}
__device__ __forceinline__ float2 upk(unsigned long long v) {
    unsigned int a, b;
    asm("mov.b64 {%0, %1}, %2;" : "=r"(a), "=r"(b) : "l"(v));
    return make_float2(__uint_as_float(a), __uint_as_float(b));
}

// ---------------- warp-mma / cp.async helpers ----------------
__device__ __forceinline__ uint32_t smem_u32(const void* p) {
    uint32_t a;
    asm("{ .reg .u64 t; cvta.to.shared.u64 t, %1; cvt.u32.u64 %0, t; }" : "=r"(a) : "l"(p));
    return a;
}
__device__ __forceinline__ void ldsm_x4(uint32_t* r, uint32_t addr) {
    asm volatile("ldmatrix.sync.aligned.m8n8.x4.shared.b16 {%0,%1,%2,%3}, [%4];"
        : "=r"(r[0]), "=r"(r[1]), "=r"(r[2]), "=r"(r[3]) : "r"(addr));
}
__device__ __forceinline__ void mma16816(float* d, const uint32_t* a, const uint32_t* b) {
    asm volatile(
        "mma.sync.aligned.m16n8k16.row.col.f32.f16.f16.f32 "
        "{%0,%1,%2,%3}, {%4,%5,%6,%7}, {%8,%9}, {%0,%1,%2,%3};"
        : "+f"(d[0]), "+f"(d[1]), "+f"(d[2]), "+f"(d[3])
        : "r"(a[0]), "r"(a[1]), "r"(a[2]), "r"(a[3]), "r"(b[0]), "r"(b[1]));
}
__device__ __forceinline__ void cp_async16(uint32_t dst, const void* src, bool valid) {
    int sz = valid ? 16 : 0;
    asm volatile("cp.async.cg.shared.global [%0], [%1], 16, %2;"
                 :: "r"(dst), "l"(src), "r"(sz) : "memory");
}
__device__ __forceinline__ void cp_commit() {
    asm volatile("cp.async.commit_group;" ::: "memory");
}
__device__ __forceinline__ void cp_wait_all() {
    asm volatile("cp.async.wait_group 0;" ::: "memory");
}

// =====================================================================
// Prep 1: split x*16 into 2 fp16 parts, layout [s][b*128+R][px*64+cin]
// =====================================================================
__global__ __launch_bounds__(256) void xsplit_kernel(const float* __restrict__ x)
{
    __shared__ float tile[64 * 128];
    const int R = blockIdx.x, b = blockIdx.y;
    const int tid = threadIdx.x;

    for (int e = tid; e < 8192; e += 256) {
        int cin = e >> 7, px = e & 127;
        tile[e] = x[((size_t)(b * 64 + cin) * 128 + R) * 128 + px];
    }
    __syncthreads();

    const size_t rowbase = ((size_t)b * 128 + R) * 8192;
    for (int e = tid; e < 4096; e += 256) {
        int e2 = e * 2;
        int px = e2 >> 6, cin0 = e2 & 63;
        float f0 = tile[cin0 * 128 + px] * 16.f;
        float f1 = tile[(cin0 + 1) * 128 + px] * 16.f;
        __half h10 = __float2half_rn(f0);
        __half h11 = __float2half_rn(f1);
        __half h20 = __float2half_rn(f0 - __half2float(h10));
        __half h21 = __float2half_rn(f1 - __half2float(h11));
        size_t eb = rowbase + e2;
        g_xs[eb] = h10; g_xs[eb + 1] = h11;
        g_xs[XS_ELEMS_PER_SPLIT + eb]     = h20;
        g_xs[XS_ELEMS_PER_SPLIT + eb + 1] = h21;
    }
}

// =====================================================================
// Prep 2: split + pre-swizzle weights (w*64): g_wsw[pass*9+tap]
// =====================================================================
__global__ __launch_bounds__(256) void wprep_kernel(const float* __restrict__ w1)
{
    const int t = blockIdx.x;          // 0..17 = pass*9 + tap
    const int pass = t / 9, tap = t - pass * 9;
    const int tid = threadIdx.x;
    for (int e = tid; e < 4096; e += 256) {
        int oc = e >> 6, cin = e & 63;
        float f = w1[oc * 576 + cin * 9 + tap] * 64.f;
        __half h1 = __float2half_rn(f);
        __half out = pass ? __float2half_rn(f - __half2float(h1)) : h1;
        uint32_t o = SW128((uint32_t)e * 2);
        g_wsw[(size_t)t * 4096 + (o >> 1)] = out;
    }
}

// =====================================================================
// conv via warp-level mma.sync (fp16, 4-term), SINGLE fused kernel.
// Grid (16 rowgroups, 2 oc-halves, 16 batches); 512 threads / 16 warps:
//   warp = (px-group w&7: 16 px) x (oc-quarter w>>3: 16 oc of CTA's 32).
// B: 18 (pass,tap) half-tiles of 4KB (this CTA's 32 oc).
// A: 4-slot ring, cp.async staged.
// All 4 split-product terms accumulate in registers; one epilogue.
// =====================================================================
#define BT_OFF 0u
#define AT_OFF 73728u
#define SLOT_STRIDE 33792u
#define SPLIT_STRIDE 16896u
#define CONVM_SMEM (73728 + 4 * 33792)
#define CONV_THREADS 512

__device__ __forceinline__ void cp_a_row(char* smem, int b, int R, int slot, int tid) {
    #pragma unroll
    for (int j = 0; j < 5; j++) {
        int c = j * CONV_THREADS + tid;
        if (c < 2080) {
            int s = (c >= 1040) ? 1 : 0;
            int r = c - s * 1040;
            int px_dst = r >> 3;
            int w16 = (r & 7) * 16;
            int px_src = px_dst - 1;
            bool valid = (R >= 0 && R < 128 && px_src >= 0 && px_src < 128);
            const char* src = (const char*)g_xs
                + (size_t)s * XS_ELEMS_PER_SPLIT * 2
                + (valid ? ((((size_t)b * 128 + R) * 8192 + (size_t)px_src * 64) * 2 + w16) : 0);
            uint32_t o = ((uint32_t)px_dst) * 128 + (uint32_t)w16;
            uint32_t dst = smem_u32(smem + AT_OFF + slot * SLOT_STRIDE
                                    + s * SPLIT_STRIDE + SW128(o));
            cp_async16(dst, src, valid);
        }
    }
}

__global__ __launch_bounds__(CONV_THREADS, 1) void conv_mma_kernel(const float* __restrict__ b1)
{
    extern __shared__ char smem[];
    const uint32_t sb = smem_u32(smem);
    const int g = blockIdx.x, ochalf = blockIdx.y, b = blockIdx.z;
    const int tid = threadIdx.x;
    const int w = tid >> 5, lane = tid & 31;
    const int wpx = w & 7;          // px group (16 px)
    const int woc = w >> 3;         // oc quarter within CTA's 32 (16 oc)
    const int Y0 = g * 8;
    const int q = lane >> 3, rr = lane & 7;

    const uint32_t a_row = (uint32_t)(wpx * 16 + rr + 8 * (q & 1));  // tile row = px + kx
    const uint32_t a_sub = (uint32_t)(16 * (q >> 1));
    const uint32_t b_base = (uint32_t)((8 * (q >> 1) + rr) * 128 + 16 * (q & 1))
                          + (uint32_t)woc * 2048u;
    const int px0 = wpx * 16 + (lane >> 2);
    const int oc0 = ochalf * 32 + woc * 16 + 2 * (lane & 3);
    float* gout = g_featc + (size_t)b * 64 * HW;

    // stage B half-tiles: 18 x 4KB (this CTA's 32-oc slice of each 8KB tile)
    for (int idx = tid; idx < 4608; idx += CONV_THREADS) {
        int t = idx >> 8;                 // 0..17
        int u = idx & 255;                // 16B unit
        *(uint4*)(smem + BT_OFF + (uint32_t)(t * 4096 + u * 16)) =
            __ldg((const uint4*)((const char*)g_wsw + (size_t)t * 8192
                                 + (size_t)ochalf * 4096 + (size_t)u * 16));
    }
    // prologue: stage rows Y0-1, Y0, Y0+1 into slots (R+1)&3
    for (int R = Y0 - 1; R <= Y0 + 1; R++) {
        cp_a_row(smem, b, R, (R + 1) & 3, tid);
    }
    cp_commit();
    cp_wait_all();
    __syncthreads();

    for (int r0 = 0; r0 < 8; r0++) {
        const int y = Y0 + r0;
        if (r0 < 7) {
            cp_a_row(smem, b, y + 2, (y + 3) & 3, tid);
            cp_commit();
        }

        float acc[2][4];
        #pragma unroll
        for (int i = 0; i < 2; i++)
            #pragma unroll
            for (int j = 0; j < 4; j++) acc[i][j] = 0.f;

        #pragma unroll
        for (int ky = 0; ky < 3; ky++) {
            const uint32_t slotb = sb + AT_OFF + (uint32_t)(((y + ky) & 3) * SLOT_STRIDE);
            #pragma unroll
            for (int kc = 0; kc < 4; kc++) {
                #pragma unroll
                for (int kx = 0; kx < 3; kx++) {
                    uint32_t o = (a_row + kx) * 128 + a_sub + 32 * kc;
                    uint32_t a1f[4], a2f[4];
                    ldsm_x4(a1f, slotb + SW128(o));
                    ldsm_x4(a2f, slotb + SPLIT_STRIDE + SW128(o));
                    const uint32_t boff = SW128(b_base + 32 * kc);
                    const uint32_t tile1 = sb + BT_OFF + (uint32_t)((ky * 3 + kx) * 4096);
                    const uint32_t tile2 = tile1 + 9u * 4096u;
                    uint32_t bw1[4], bw2[4];
                    ldsm_x4(bw1, tile1 + boff);
                    ldsm_x4(bw2, tile2 + boff);
                    mma16816(acc[0], a1f, bw1);
                    mma16816(acc[1], a1f, bw1 + 2);
                    mma16816(acc[0], a2f, bw1);
                    mma16816(acc[1], a2f, bw1 + 2);
                    mma16816(acc[0], a1f, bw2);
                    mma16816(acc[1], a1f, bw2 + 2);
                    mma16816(acc[0], a2f, bw2);
                    mma16816(acc[1], a2f, bw2 + 2);
                }
            }
        }

        // single epilogue: unscale + bias + relu
        #pragma unroll
        for (int nt = 0; nt < 2; nt++) {
            const int oc = oc0 + nt * 8;
            const float ba = __ldg(b1 + oc), bbv = __ldg(b1 + oc + 1);
            float* p0 = gout + (size_t)oc * HW + y * 128 + px0;
            float* p1 = p0 + HW;
            p0[0] = fmaxf(acc[nt][0] * OUT_SCALE + ba,  0.f);
            p1[0] = fmaxf(acc[nt][1] * OUT_SCALE + bbv, 0.f);
            p0[8] = fmaxf(acc[nt][2] * OUT_SCALE + ba,  0.f);
            p1[8] = fmaxf(acc[nt][3] * OUT_SCALE + bbv, 0.f);
        }
        cp_wait_all();
        __syncthreads();
    }
}

// =====================================================================
// Fused 1x1 conv (64->80) + LOGIT-SPACE 3x3 peak + argmax.
// =====================================================================
__global__ __launch_bounds__(128, 4) void clspeak_kernel(
    const float* __restrict__ w2, const float* __restrict__ b2)
{
    __shared__ float s_w[80 * 64];
    __shared__ float s_b[80];
    __shared__ float s_cls[20 * 104];

    const int bx = blockIdx.x, by = blockIdx.y, b = blockIdx.z;
    const int ox = bx * 8, oy = by * 8;
    const int tid = threadIdx.x;
    const float NEG = -1e30f;

    for (int e = tid; e < 80 * 64; e += 128) s_w[e] = w2[e];
    if (tid < 80) s_b[tid] = b2[tid];

    unsigned long long fd[32];
    bool inimg = false;
    if (tid < 100) {
        int iy = tid / 10, ix = tid - iy * 10;
        int gy = oy + iy - 1, gx = ox + ix - 1;
        inimg = (gy >= 0 && gy < HH && gx >= 0 && gx < WW);
        const float* fp = g_featc + (size_t)b * 64 * HW + gy * WW + gx;
        #pragma unroll
        for (int i = 0; i < 32; i++) {
            float a = inimg ? fp[(2 * i) * HW]     : 0.f;
            float c = inimg ? fp[(2 * i + 1) * HW] : 0.f;
            fd[i] = pk2(a, c);
        }
    }
    __syncthreads();

    const int py = (tid >> 3) + 1, px = (tid & 7) + 1;
    const int pp = py * 10 + px;
    float best = NEG;
    int cat = 0;

    for (int g = 0; g < 4; g++) {
        if (tid < 100) {
            #pragma unroll
            for (int cp = 0; cp < 10; cp++) {
                const int c0 = g * 20 + 2 * cp;
                unsigned long long a0 = 0ull, a1 = 0ull;
                const ulonglong2* w0 = (const ulonglong2*)(s_w + c0 * 64);
                const ulonglong2* w1 = (const ulonglong2*)(s_w + (c0 + 1) * 64);
                #pragma unroll
                for (int i = 0; i < 16; i++) {
                    ulonglong2 wa = w0[i];
                    ulonglong2 wb = w1[i];
                    a0 = fma2(fd[2 * i],     wa.x, a0);
                    a0 = fma2(fd[2 * i + 1], wa.y, a0);
                    a1 = fma2(fd[2 * i],     wb.x, a1);
                    a1 = fma2(fd[2 * i + 1], wb.y, a1);
                }
                float2 u0 = upk(a0), u1 = upk(a1);
                float v0 = u0.x + u0.y + s_b[c0];
                float v1 = u1.x + u1.y + s_b[c0 + 1];
                if (!inimg) { v0 = NEG; v1 = NEG; }
                s_cls[(2 * cp)     * 104 + tid] = v0;
                s_cls[(2 * cp + 1) * 104 + tid] = v1;
            }
        }
        __syncthreads();
        if (tid < 64) {
            #pragma unroll 4
            for (int c = 0; c < 20; c++) {
                const float* row = s_cls + c * 104;
                float v = row[pp];
                float m = v;
                m = fmaxf(m, row[pp - 11]); m = fmaxf(m, row[pp - 10]); m = fmaxf(m, row[pp - 9]);
                m = fmaxf(m, row[pp - 1]);                               m = fmaxf(m, row[pp + 1]);
                m = fmaxf(m, row[pp + 9]);  m = fmaxf(m, row[pp + 10]); m = fmaxf(m, row[pp + 11]);
                float k = (v == m) ? v : NEG;
                if (k > best) { best = k; cat = g * 20 + c; }
            }
        }
        __syncthreads();
    }

    if (tid < 64) {
        int gp = (oy + py - 1) * WW + ox + px - 1;
        unsigned int u = __float_as_uint(best);
        unsigned int mu = (u & 0x80000000u) ? ~u : (u | 0x80000000u);
        g_scoreu[b * HW + gp] = mu;
        g_cat[b * HW + gp]    = cat;
    }
}

// =====================================================================
// top-100 on monotone-uint keys; writes back logits.
// =====================================================================
#define TOPK_SMEM (8192 * 4 + 1024 * 4 + HW * 8)
__global__ __launch_bounds__(1024) void topk_kernel()
{
    extern __shared__ int smi[];
    int* hist = smi;
    int* suf  = smi + 8192;
    unsigned long long* cand = (unsigned long long*)(smi + 8192 + 1024);
    __shared__ int s_tstar, s_T, s_cnt;

    const int b = blockIdx.x;
    const int tid = threadIdx.x;
    const unsigned int* s = g_scoreu + b * HW;

    for (int i = tid; i < 8192; i += 1024) hist[i] = 0;
    if (tid == 0) s_cnt = 0;
    __syncthreads();

    for (int j = tid; j < HW; j += 1024) {
        unsigned int mu = s[j];
        atomicAdd(&hist[mu >> 19], 1);
    }
    __syncthreads();

    int seg = 0;
    #pragma unroll
    for (int k = 0; k < 8; k++) seg += hist[tid * 8 + k];
    suf[tid] = seg;
    __syncthreads();
    for (int off = 1; off < 1024; off <<= 1) {
        int v = suf[tid];
        int add = (tid + off < 1024) ? suf[tid + off] : 0;
        __syncthreads();
        suf[tid] = v + add;
        __syncthreads();
    }
    if (suf[tid] >= KTOP && (tid == 1023 || suf[tid + 1] < KTOP)) s_tstar = tid;
    __syncthreads();
    if (tid == s_tstar) {
        int acc = (tid == 1023) ? 0 : suf[tid + 1];
        for (int bb = tid * 8 + 7; bb >= tid * 8; bb--) {
            acc += hist[bb];
            if (acc >= KTOP) { s_T = bb; break; }
        }
    }
    __syncthreads();
    const int T = s_T;

    for (int j = tid; j < HW; j += 1024) {
        unsigned int mu = s[j];
        if ((int)(mu >> 19) >= T) {
            int pos = atomicAdd(&s_cnt, 1);
            cand[pos] = ((unsigned long long)mu << 32) | (unsigned long long)(HW - j);
        }
    }
    __syncthreads();
    const int N = s_cnt;

    for (int i = tid; i < N; i += 1024) {
        unsigned long long key = cand[i];
        int rank = 0;
        for (int j = 0; j < N; j++) rank += (cand[j] > key);
        if (rank < KTOP) {
            unsigned int mu = (unsigned int)(key >> 32);
            unsigned int u = (mu & 0x80000000u) ? (mu ^ 0x80000000u) : ~mu;
            g_tscore[b * KTOP + rank] = __uint_as_float(u);   // logit
            g_tind[b * KTOP + rank]   = HW - (int)(key & 0xFFFFFFFFull);
        }
    }
}

// =====================================================================
// reg/wh at selected points (PTS=2)
// =====================================================================
#define PTS 2
__global__ __launch_bounds__(128) void point_kernel(
    const float* __restrict__ x,
    const float* __restrict__ rw1, const float* __restrict__ rb1,
    const float* __restrict__ rw2, const float* __restrict__ rb2,
    const float* __restrict__ ww1, const float* __restrict__ wb1,
    const float* __restrict__ ww2, const float* __restrict__ wb2)
{
    __shared__ float sx[PTS][576];
    __shared__ int   sp[PTS];
    __shared__ float sfa[128][PTS + 1];
    __shared__ float sres[PTS][4];

    const int g = blockIdx.x, b = blockIdx.y;
    const int tid = threadIdx.x;

    if (tid < PTS) sp[tid] = g_tind[b * KTOP + g * PTS + tid];
    __syncthreads();

    for (int e = tid; e < PTS * 576; e += 128) {
        int pt = e / 576;
        int r  = e - pt * 576;
        int c  = r / 9;
        int k9 = r - c * 9;
        int dy = k9 / 3 - 1, dx = k9 % 3 - 1;
        int p = sp[pt];
        int gy = (p >> 7) + dy, gx = (p & 127) + dx;
        float v = 0.f;
        if (gy >= 0 && gy < HH && gx >= 0 && gx < WW)
            v = x[((size_t)b * CINC + c) * HW + gy * WW + gx];
        sx[pt][r] = v;
    }
    __syncthreads();

    const float* wrow = (tid < 64) ? (rw1 + tid * 576) : (ww1 + (tid - 64) * 576);
    float bias = (tid < 64) ? rb1[tid] : wb1[tid - 64];
    float acc[PTS];
    #pragma unroll
    for (int pt = 0; pt < PTS; pt++) acc[pt] = bias;

    for (int j = 0; j < 576; j += 4) {
        float4 w4 = *(const float4*)(wrow + j);
        #pragma unroll
        for (int q = 0; q < 4; q++) {
            float w = (q == 0) ? w4.x : (q == 1) ? w4.y : (q == 2) ? w4.z : w4.w;
            #pragma unroll
            for (int pt = 0; pt < PTS; pt++)
                acc[pt] = fmaf(w, sx[pt][j + q], acc[pt]);
        }
    }
    #pragma unroll
    for (int pt = 0; pt < PTS; pt++) sfa[tid][pt] = fmaxf(acc[pt], 0.f);
    __syncthreads();

    if (tid < PTS * 4) {
        int pt = tid >> 2, o = tid & 3;
        float sv;
        if (o < 2) {
            sv = rb2[o];
            for (int i = 0; i < 64; i++) sv = fmaf(sfa[i][pt], rw2[o * 64 + i], sv);
            sv = 1.f / (1.f + expf(-sv));
        } else {
            int oo = o - 2;
            sv = wb2[oo];
            for (int i = 0; i < 64; i++) sv = fmaf(sfa[64 + i][pt], ww2[oo * 64 + i], sv);
            sv = expf(sv);
        }
        sres[pt][o] = sv;
    }
    __syncthreads();

    if (tid < PTS) {
        int p = sp[tid];
        float cx = (float)(p & 127) + sres[tid][0];
        float cy = (float)(p >> 7)  + sres[tid][1];
        float wv = sres[tid][2], hv = sres[tid][3];
        int k = b * KTOP + g * PTS + tid;
        g_boxes[k * 4 + 0] = (cx - wv * 0.5f) * 4.f;
        g_boxes[k * 4 + 1] = (cy - hv * 0.5f) * 4.f;
        g_boxes[k * 4 + 2] = (cx + wv * 0.5f) * 4.f;
        g_boxes[k * 4 + 3] = (cy + hv * 0.5f) * 4.f;
    }
}

// =====================================================================
// NMS + output (sigmoid applied here to the selected logits)
// =====================================================================
__global__ __launch_bounds__(128) void nms_kernel(float* __restrict__ out)
{
    const int b = blockIdx.x;
    const int tid = threadIdx.x;
    __shared__ float bx[KTOP][4];
    __shared__ float barea[KTOP];
    __shared__ int keep[KTOP];

    float score = 0.f; int cat = 0;
    if (tid < KTOP) {
        int k = b * KTOP + tid;
        float logit = g_tscore[k];
        score = 1.f / (1.f + expf(-logit));
        cat   = g_cat[b * HW + g_tind[k]];
        float x1 = g_boxes[k * 4 + 0], y1 = g_boxes[k * 4 + 1];
        float x2 = g_boxes[k * 4 + 2], y2 = g_boxes[k * 4 + 3];
        bx[tid][0] = x1; bx[tid][1] = y1; bx[tid][2] = x2; bx[tid][3] = y2;
        barea[tid] = (x2 - x1) * (y2 - y1);
        keep[tid] = (score > 0.2f) ? 1 : 0;
    }
    __syncthreads();

    for (int i = 0; i < KTOP - 1; i++) {
        if (tid < KTOP && tid > i && keep[i]) {
            float xx1 = fmaxf(bx[i][0], bx[tid][0]);
            float yy1 = fmaxf(bx[i][1], bx[tid][1]);
            float xx2 = fminf(bx[i][2], bx[tid][2]);
            float yy2 = fminf(bx[i][3], bx[tid][3]);
            float iw = fmaxf(xx2 - xx1, 0.f);
            float ih = fmaxf(yy2 - yy1, 0.f);
            float inter = iw * ih;
            float iou = inter / (barea[i] + barea[tid] - inter + 1e-9f);
            if (iou > 0.5f) keep[tid] = 0;
        }
        __syncthreads();
    }

    if (tid < KTOP) {
        int base = b * KTOP + tid;
        out[base * 4 + 0] = bx[tid][0];
        out[base * 4 + 1] = bx[tid][1];
        out[base * 4 + 2] = bx[tid][2];
        out[base * 4 + 3] = bx[tid][3];
        out[6400 + base] = (float)cat;
        out[8000 + base] = score;
        out[9600 + base] = keep[tid] ? 1.f : 0.f;
    }
}

// =====================================================================
extern "C" void kernel_launch(void* const* d_in, const int* in_sizes, int n_in,
                              void* d_out, int out_size)
{
    const float* x      = (const float*)d_in[0];
    const float* cls_w1 = (const float*)d_in[1];
    const float* cls_b1 = (const float*)d_in[2];
    const float* cls_w2 = (const float*)d_in[3];
    const float* cls_b2 = (const float*)d_in[4];
    const float* reg_w1 = (const float*)d_in[5];
    const float* reg_b1 = (const float*)d_in[6];
    const float* reg_w2 = (const float*)d_in[7];
    const float* reg_b2 = (const float*)d_in[8];
    const float* wh_w1  = (const float*)d_in[9];
    const float* wh_b1  = (const float*)d_in[10];
    const float* wh_w2  = (const float*)d_in[11];
    const float* wh_b2  = (const float*)d_in[12];
    float* out = (float*)d_out;

    cudaFuncSetAttribute(conv_mma_kernel, cudaFuncAttributeMaxDynamicSharedMemorySize, CONVM_SMEM);
    cudaFuncSetAttribute(topk_kernel, cudaFuncAttributeMaxDynamicSharedMemorySize, TOPK_SMEM);

    xsplit_kernel<<<dim3(128, BATCH), 256>>>(x);
    wprep_kernel<<<18, 256>>>(cls_w1);
    conv_mma_kernel<<<dim3(16, 2, BATCH), CONV_THREADS, CONVM_SMEM>>>(cls_b1);
    clspeak_kernel<<<dim3(16, 16, BATCH), 128>>>(cls_w2, cls_b2);
    topk_kernel<<<BATCH, 1024, TOPK_SMEM>>>();
    point_kernel<<<dim3(50, BATCH), 128>>>(x, reg_w1, reg_b1, reg_w2, reg_b2,
                                           wh_w1, wh_b1, wh_w2, wh_b2);
    nms_kernel<<<BATCH, 128>>>(out);
}